// round 9
// baseline (speedup 1.0000x reference)
#include <cuda_runtime.h>
#include <cuda_bf16.h>
#include <stdint.h>
#include <math.h>

#define HW 16384
#define RLEN 9088         // padded row: 448 + 128*64 + 448 elems
#define NROWS 144         // h = -8 .. 135
typedef unsigned u32; typedef unsigned long long u64;

// ---------------- device scratch (zero-initialized; pads never written) ----
__device__ __align__(256) __nv_bfloat16 g_xA_h[12 * NROWS * RLEN];
__device__ __align__(256) __nv_bfloat16 g_xA_l[12 * NROWS * RLEN];
__device__ __align__(256) __nv_bfloat16 g_cA_h[16 * NROWS * RLEN];
__device__ __align__(256) __nv_bfloat16 g_cA_l[16 * NROWS * RLEN];
__device__ __align__(256) __nv_bfloat16 g_wb_h[4 * 27 * 4096];
__device__ __align__(256) __nv_bfloat16 g_wb_l[4 * 27 * 4096];
__device__ __align__(256) __nv_bfloat16 g_wo_h[36 * 4096];
__device__ __align__(256) __nv_bfloat16 g_wo_l[36 * 4096];

// ---------------- PTX helpers ----------------------------------------------
__device__ __forceinline__ u32 s2u(const void* p){
    u32 a; asm("{ .reg .u64 t; cvta.to.shared.u64 t, %1; cvt.u32.u64 %0, t; }"
               : "=r"(a) : "l"(p)); return a;
}
#define CP16(dst, src) \
    asm volatile("cp.async.cg.shared.global [%0], [%1], 16;" :: "r"(dst), "l"(src) : "memory")
#define CP_COMMIT() asm volatile("cp.async.commit_group;" ::: "memory")
#define CP_WAIT1()  asm volatile("cp.async.wait_group 1;" ::: "memory")
#define LDX4(r, a) \
    asm volatile("ldmatrix.sync.aligned.m8n8.x4.shared.b16 {%0,%1,%2,%3}, [%4];" \
        : "=r"((r)[0]), "=r"((r)[1]), "=r"((r)[2]), "=r"((r)[3]) : "r"(a))
#define MMA(d, a, b0, b1) \
    asm("mma.sync.aligned.m16n8k16.row.col.f32.bf16.bf16.f32 " \
        "{%0,%1,%2,%3},{%4,%5,%6,%7},{%8,%9},{%0,%1,%2,%3};" \
        : "+f"((d)[0]), "+f"((d)[1]), "+f"((d)[2]), "+f"((d)[3]) \
        : "r"((a)[0]), "r"((a)[1]), "r"((a)[2]), "r"((a)[3]), "r"(b0), "r"(b1))

__device__ __forceinline__ void split2(float v0, float v1, u32& hw, u32& lw){
    __nv_bfloat16 h0 = __float2bfloat16(v0);
    __nv_bfloat16 h1 = __float2bfloat16(v1);
    __nv_bfloat16 l0 = __float2bfloat16(v0 - __bfloat162float(h0));
    __nv_bfloat16 l1 = __float2bfloat16(v1 - __bfloat162float(h1));
    hw = (u32)*(unsigned short*)&h0 | ((u32)*(unsigned short*)&h1 << 16);
    lw = (u32)*(unsigned short*)&l0 | ((u32)*(unsigned short*)&l1 << 16);
}

// ---------------- stage 1: mask conv + softmax ------------------------------
__global__ void mask_kernel(const float* __restrict__ x, const float* __restrict__ mw,
                            const float* __restrict__ mb, float* __restrict__ masks)
{
    __shared__ float s_mw[3*64*9];
    for (int i = threadIdx.x; i < 3*64*9; i += 256) s_mw[i] = mw[i];
    __syncthreads();
    int gid = blockIdx.x*256 + threadIdx.x;
    int b = gid >> 14, pid = gid & (HW-1), h = pid >> 7, w = pid & 127;
    float a0 = mb[0], a1 = mb[1], a2 = mb[2];
    const float* xb = x + b*64*HW;
    for (int c = 0; c < 64; c++){
        const float* xc = xb + c*HW; const float* wc = s_mw + c*9;
        #pragma unroll
        for (int kh = 0; kh < 3; kh++){
            int hh = h + kh - 1; if ((unsigned)hh >= 128u) continue;
            #pragma unroll
            for (int kw = 0; kw < 3; kw++){
                int ww = w + kw - 1; if ((unsigned)ww >= 128u) continue;
                float v = xc[hh*128 + ww]; int t = kh*3 + kw;
                a0 = fmaf(v, wc[t], a0); a1 = fmaf(v, wc[576+t], a1); a2 = fmaf(v, wc[1152+t], a2);
            }
        }
    }
    float mx = fmaxf(a0, fmaxf(a1, a2));
    float e0 = expf(a0-mx), e1 = expf(a1-mx), e2 = expf(a2-mx);
    float inv = 1.f/(e0+e1+e2);
    masks[(b*3+0)*HW+pid] = e0*inv; masks[(b*3+1)*HW+pid] = e1*inv; masks[(b*3+2)*HW+pid] = e2*inv;
}

// ---------------- stage 2: transpose + split xm into padded layout ----------
__global__ void xmT_kernel(const float* __restrict__ x, const float* __restrict__ masks)
{
    __shared__ float sx[64*129];
    __shared__ float sm[128];
    int bx = blockIdx.x;                 // (bm<<7)|h
    int h = bx & 127, bm = bx >> 7, m = bm % 3, b = bm / 3;
    for (int idx = threadIdx.x; idx < 8192; idx += 256){
        int c = idx >> 7, w = idx & 127;
        sx[c*129 + w] = x[(b*64 + c)*HW + h*128 + w];
    }
    if (threadIdx.x < 128) sm[threadIdx.x] = masks[bm*HW + h*128 + threadIdx.x];
    __syncthreads();
    size_t base = ((size_t)bm*NROWS + (h+8))*RLEN + 448;
    for (int idx = threadIdx.x; idx < 4096; idx += 256){
        int w = idx >> 5, c2 = (idx & 31)*2;
        float v0 = sx[c2*129 + w] * sm[w];
        float v1 = sx[(c2+1)*129 + w] * sm[w];
        u32 hw, lw; split2(v0, v1, hw, lw);
        size_t e = base + (size_t)w*64 + c2;
        *(u32*)(g_xA_h + e) = hw;
        *(u32*)(g_xA_l + e) = lw;
    }
}

// ---------------- weight prep: split B tiles [tile][o][c] -------------------
__global__ void wprep_kernel(const float* __restrict__ kern, const float* __restrict__ cow)
{
    int i = blockIdx.x*256 + threadIdx.x;
    if (i < 4*27*4096){
        int tile = i >> 12, e = i & 4095, o = e >> 6, c = e & 63;
        int b = tile / 27, r = tile % 27, tap = r / 3, m = r % 3;
        float v = kern[(((b*3 + m)*64 + o)*64 + c)*9 + tap];
        __nv_bfloat16 hi = __float2bfloat16(v);
        g_wb_h[i] = hi;
        g_wb_l[i] = __float2bfloat16(v - __bfloat162float(hi));
    }
    if (i < 36*4096){
        int tile = i >> 12, e = i & 4095, o = e >> 6, c = e & 63;
        int tap = tile / 4, ch = tile % 4;
        float v = cow[(o*256 + ch*64 + c)*9 + tap];
        __nv_bfloat16 hi = __float2bfloat16(v);
        g_wo_h[i] = hi;
        g_wo_l[i] = __float2bfloat16(v - __bfloat162float(hi));
    }
}

// ---------------- MMA mainloop (512 threads, N split across warp-groups) ----
// smem (bytes): A: [buf][hi,lo] 128x72 bf16 = 18432 each -> buf stride 36864
//               B: at 73728 + [buf][hi,lo] 64x72 bf16 = 9216 each -> buf stride 18432
// total 110592 bytes.  Warps 0-7 compute o[0:32], warps 8-15 o[32:64].
template<int NS, int NCH>
__device__ __forceinline__ void mma_mainloop(
    const __nv_bfloat16* __restrict__ xah, const __nv_bfloat16* __restrict__ xal,
    const __nv_bfloat16* __restrict__ wth, const __nv_bfloat16* __restrict__ wtl,
    int d, int h, float acc[4][4])
{
    extern __shared__ __align__(16) unsigned char smraw[];
    u32 sm0 = s2u(smraw);
    const int tid = threadIdx.x, lane = tid & 31, wid = tid >> 5;
    const int mwarp = wid & 7, nhalf = wid >> 3;

    #pragma unroll
    for (int i = 0; i < 4; i++)
        #pragma unroll
        for (int j = 0; j < 4; j++) acc[i][j] = 0.f;

    auto issue = [&](int s, int buf){
        int tap = s / NCH, ch = s - tap*NCH;
        int dh = (tap/3 - 1)*d, dw = (tap%3 - 1)*d;
        size_t arow = ((size_t)ch*NROWS + (h + 8 + dh))*RLEN + 448 + (long)dw*64;
        u32 abase = sm0 + (u32)buf*36864u;
        #pragma unroll
        for (int t = 0; t < 2; t++){
            int idx = tid + t*512; int w = idx >> 3, c16 = idx & 7;
            size_t off = arow + (size_t)w*64 + c16*8;
            u32 dst = abase + (u32)(w*144 + c16*16);
            CP16(dst,          xah + off);
            CP16(dst + 18432u, xal + off);
        }
        u32 bbase = sm0 + 73728u + (u32)buf*18432u;
        const __nv_bfloat16* wsh = wth + (size_t)s*4096;
        const __nv_bfloat16* wsl = wtl + (size_t)s*4096;
        {
            int idx = tid; int o = idx >> 3, c16 = idx & 7;
            u32 dst = bbase + (u32)(o*144 + c16*16);
            CP16(dst,         wsh + o*64 + c16*8);
            CP16(dst + 9216u, wsl + o*64 + c16*8);
        }
    };

    issue(0, 0); CP_COMMIT();
    issue(1, 1); CP_COMMIT();

    const u32 a_lane = (u32)((mwarp*16 + (lane & 15))*144 + (lane >> 4)*16);
    const int br = lane & 7, bq = lane >> 3;
    const u32 b_lane0 = (u32)((br + (bq >> 1)*8)*144 + (bq & 1)*16 + nhalf*2*16*144);

    for (int s = 0; s < NS; s++){
        int buf = s & 1;
        CP_WAIT1();
        __syncthreads();
        u32 ab = sm0 + (u32)buf*36864u + a_lane;
        u32 bb = sm0 + 73728u + (u32)buf*18432u + b_lane0;
        #pragma unroll
        for (int ks = 0; ks < 4; ks++){
            u32 ah[4], al[4];
            LDX4(ah, ab + ks*32);
            LDX4(al, ab + ks*32 + 18432u);
            #pragma unroll
            for (int np = 0; np < 2; np++){
                u32 bh[4], bl[4];
                u32 ba = bb + (u32)(np*16*144) + ks*32;
                LDX4(bh, ba);
                LDX4(bl, ba + 9216u);
                MMA(acc[2*np],   ah, bh[0], bh[1]);
                MMA(acc[2*np],   ah, bl[0], bl[1]);
                MMA(acc[2*np],   al, bh[0], bh[1]);
                MMA(acc[2*np+1], ah, bh[2], bh[3]);
                MMA(acc[2*np+1], ah, bl[2], bl[3]);
                MMA(acc[2*np+1], al, bh[2], bh[3]);
            }
        }
        __syncthreads();
        if (s + 2 < NS) issue(s + 2, buf);
        CP_COMMIT();
    }
}

// ---------------- branch conv: writes split cat tiles ------------------------
__global__ void __launch_bounds__(512, 1)
branch_mma()
{
    int bx = blockIdx.x;                  // h | di<<7 | b<<9
    int h = bx & 127, di = (bx >> 7) & 3, b = bx >> 9;
    int d = 2*di + 1;

    float acc[4][4];
    mma_mainloop<27, 3>(g_xA_h + (size_t)(b*3)*NROWS*RLEN,
                        g_xA_l + (size_t)(b*3)*NROWS*RLEN,
                        g_wb_h + (size_t)b*27*4096,
                        g_wb_l + (size_t)b*27*4096, d, h, acc);

    const int lane = threadIdx.x & 31, wid = threadIdx.x >> 5;
    const int w0 = (wid & 7)*16, g = lane >> 2, tig = lane & 3;
    const int obase = (wid >> 3)*32;
    size_t cb = ((size_t)(b*4 + di)*NROWS + (h + 8))*RLEN + 448;
    #pragma unroll
    for (int nt = 0; nt < 4; nt++){
        int o = obase + nt*8 + 2*tig;
        u32 hw, lw;
        split2(acc[nt][0], acc[nt][1], hw, lw);
        size_t e0 = cb + (size_t)(w0 + g)*64 + o;
        *(u32*)(g_cA_h + e0) = hw; *(u32*)(g_cA_l + e0) = lw;
        split2(acc[nt][2], acc[nt][3], hw, lw);
        size_t e1 = cb + (size_t)(w0 + g + 8)*64 + o;
        *(u32*)(g_cA_h + e1) = hw; *(u32*)(g_cA_l + e1) = lw;
    }
}

// ---------------- out conv + bias + BN + ReLU --------------------------------
__global__ void __launch_bounds__(512, 1)
out_mma(const float* __restrict__ cob, const float* __restrict__ gamma,
        const float* __restrict__ beta, const float* __restrict__ mean,
        const float* __restrict__ var, float* __restrict__ out)
{
    __shared__ float sInv[64], sAdd[64], sBias[64];
    int bx = blockIdx.x;                  // h | b<<7
    int h = bx & 127, b = bx >> 7;
    if (threadIdx.x < 64){
        int o = threadIdx.x;
        float inv = gamma[o] * rsqrtf(var[o] + 1e-5f);
        sInv[o] = inv; sAdd[o] = beta[o] - mean[o]*inv; sBias[o] = cob[o];
    }

    float acc[4][4];
    mma_mainloop<36, 4>(g_cA_h + (size_t)(b*4)*NROWS*RLEN,
                        g_cA_l + (size_t)(b*4)*NROWS*RLEN,
                        g_wo_h, g_wo_l, 1, h, acc);

    const int lane = threadIdx.x & 31, wid = threadIdx.x >> 5;
    const int w0 = (wid & 7)*16, g = lane >> 2, tig = lane & 3;
    const int obase = (wid >> 3)*32;
    #pragma unroll
    for (int nt = 0; nt < 4; nt++){
        int o = obase + nt*8 + 2*tig;
        float i0 = sInv[o], a0 = sAdd[o], c0 = sBias[o];
        float i1 = sInv[o+1], a1 = sAdd[o+1], c1 = sBias[o+1];
        float* p0 = out + ((size_t)(b*64 + o))*HW + h*128;
        float* p1 = p0 + HW;
        p0[w0 + g]     = fmaxf((acc[nt][0] + c0)*i0 + a0, 0.f);
        p1[w0 + g]     = fmaxf((acc[nt][1] + c1)*i1 + a1, 0.f);
        p0[w0 + g + 8] = fmaxf((acc[nt][2] + c0)*i0 + a0, 0.f);
        p1[w0 + g + 8] = fmaxf((acc[nt][3] + c1)*i1 + a1, 0.f);
    }
}

// ---------------- host --------------------------------------------------------
extern "C" void kernel_launch(void* const* d_in, const int* in_sizes, int n_in,
                              void* d_out, int out_size)
{
    const float* x     = (const float*)d_in[0];
    const float* kern  = (const float*)d_in[1];
    const float* mw    = (const float*)d_in[2];
    const float* mb    = (const float*)d_in[3];
    const float* cow   = (const float*)d_in[4];
    const float* cob   = (const float*)d_in[5];
    const float* gamma = (const float*)d_in[6];
    const float* beta  = (const float*)d_in[7];
    const float* mean  = (const float*)d_in[8];
    const float* var   = (const float*)d_in[9];
    float* out   = (float*)d_out;
    float* masks = out + 4*64*HW;

    const int SMEM = 110592;
    cudaFuncSetAttribute(branch_mma, cudaFuncAttributeMaxDynamicSharedMemorySize, SMEM);
    cudaFuncSetAttribute(out_mma,    cudaFuncAttributeMaxDynamicSharedMemorySize, SMEM);

    mask_kernel<<<256, 256>>>(x, mw, mb, masks);
    xmT_kernel<<<1536, 256>>>(x, masks);
    wprep_kernel<<<1728, 256>>>(kern, cow);
    branch_mma<<<2048, 512, SMEM>>>();
    out_mma<<<512, 512, SMEM>>>(cob, gamma, beta, mean, var, out);
}

// round 10
// speedup vs baseline: 1.2149x; 1.2149x over previous
#include <cuda_runtime.h>
#include <cuda_bf16.h>
#include <stdint.h>
#include <math.h>

#define HW 16384
#define RLEN 9088         // padded row: 448 + 128*64 + 448 elems
#define NROWS 144         // h = -8 .. 135
#define BUFSZ 55296u      // one pipeline stage: A hi/lo (36864) + B hi/lo (18432)
#define A_LO  18432u
#define B_OFF 36864u
#define B_LO  9216u
typedef unsigned u32; typedef unsigned long long u64;

// ---------------- device scratch (zero-initialized; pads never written) ----
__device__ __align__(256) __nv_bfloat16 g_xA_h[12 * NROWS * RLEN];
__device__ __align__(256) __nv_bfloat16 g_xA_l[12 * NROWS * RLEN];
__device__ __align__(256) __nv_bfloat16 g_cA_h[16 * NROWS * RLEN];
__device__ __align__(256) __nv_bfloat16 g_cA_l[16 * NROWS * RLEN];
__device__ __align__(256) __nv_bfloat16 g_wb_h[4 * 27 * 4096];
__device__ __align__(256) __nv_bfloat16 g_wb_l[4 * 27 * 4096];
__device__ __align__(256) __nv_bfloat16 g_wo_h[36 * 4096];
__device__ __align__(256) __nv_bfloat16 g_wo_l[36 * 4096];

// ---------------- PTX helpers ----------------------------------------------
__device__ __forceinline__ u32 s2u(const void* p){
    u32 a; asm("{ .reg .u64 t; cvta.to.shared.u64 t, %1; cvt.u32.u64 %0, t; }"
               : "=r"(a) : "l"(p)); return a;
}
#define CP16(dst, src) \
    asm volatile("cp.async.cg.shared.global [%0], [%1], 16;" :: "r"(dst), "l"(src) : "memory")
#define CP_COMMIT() asm volatile("cp.async.commit_group;" ::: "memory")
#define CP_WAIT1()  asm volatile("cp.async.wait_group 1;" ::: "memory")
#define LDX4(r, a) \
    asm volatile("ldmatrix.sync.aligned.m8n8.x4.shared.b16 {%0,%1,%2,%3}, [%4];" \
        : "=r"((r)[0]), "=r"((r)[1]), "=r"((r)[2]), "=r"((r)[3]) : "r"(a))
#define MMA(d, a, b0, b1) \
    asm("mma.sync.aligned.m16n8k16.row.col.f32.bf16.bf16.f32 " \
        "{%0,%1,%2,%3},{%4,%5,%6,%7},{%8,%9},{%0,%1,%2,%3};" \
        : "+f"((d)[0]), "+f"((d)[1]), "+f"((d)[2]), "+f"((d)[3]) \
        : "r"((a)[0]), "r"((a)[1]), "r"((a)[2]), "r"((a)[3]), "r"(b0), "r"(b1))

__device__ __forceinline__ void split2(float v0, float v1, u32& hw, u32& lw){
    __nv_bfloat16 h0 = __float2bfloat16(v0);
    __nv_bfloat16 h1 = __float2bfloat16(v1);
    __nv_bfloat16 l0 = __float2bfloat16(v0 - __bfloat162float(h0));
    __nv_bfloat16 l1 = __float2bfloat16(v1 - __bfloat162float(h1));
    hw = (u32)*(unsigned short*)&h0 | ((u32)*(unsigned short*)&h1 << 16);
    lw = (u32)*(unsigned short*)&l0 | ((u32)*(unsigned short*)&l1 << 16);
}

// ---------------- stage 1: mask conv + softmax ------------------------------
__global__ void mask_kernel(const float* __restrict__ x, const float* __restrict__ mw,
                            const float* __restrict__ mb, float* __restrict__ masks)
{
    __shared__ float s_mw[3*64*9];
    for (int i = threadIdx.x; i < 3*64*9; i += 256) s_mw[i] = mw[i];
    __syncthreads();
    int gid = blockIdx.x*256 + threadIdx.x;
    int b = gid >> 14, pid = gid & (HW-1), h = pid >> 7, w = pid & 127;
    float a0 = mb[0], a1 = mb[1], a2 = mb[2];
    const float* xb = x + b*64*HW;
    for (int c = 0; c < 64; c++){
        const float* xc = xb + c*HW; const float* wc = s_mw + c*9;
        #pragma unroll
        for (int kh = 0; kh < 3; kh++){
            int hh = h + kh - 1; if ((unsigned)hh >= 128u) continue;
            #pragma unroll
            for (int kw = 0; kw < 3; kw++){
                int ww = w + kw - 1; if ((unsigned)ww >= 128u) continue;
                float v = xc[hh*128 + ww]; int t = kh*3 + kw;
                a0 = fmaf(v, wc[t], a0); a1 = fmaf(v, wc[576+t], a1); a2 = fmaf(v, wc[1152+t], a2);
            }
        }
    }
    float mx = fmaxf(a0, fmaxf(a1, a2));
    float e0 = expf(a0-mx), e1 = expf(a1-mx), e2 = expf(a2-mx);
    float inv = 1.f/(e0+e1+e2);
    masks[(b*3+0)*HW+pid] = e0*inv; masks[(b*3+1)*HW+pid] = e1*inv; masks[(b*3+2)*HW+pid] = e2*inv;
}

// ---------------- stage 2: transpose + split xm into padded layout ----------
__global__ void xmT_kernel(const float* __restrict__ x, const float* __restrict__ masks)
{
    __shared__ float sx[64*129];
    __shared__ float sm[128];
    int bx = blockIdx.x;                 // (bm<<7)|h
    int h = bx & 127, bm = bx >> 7, m = bm % 3, b = bm / 3;
    for (int idx = threadIdx.x; idx < 8192; idx += 256){
        int c = idx >> 7, w = idx & 127;
        sx[c*129 + w] = x[(b*64 + c)*HW + h*128 + w];
    }
    if (threadIdx.x < 128) sm[threadIdx.x] = masks[bm*HW + h*128 + threadIdx.x];
    __syncthreads();
    size_t base = ((size_t)bm*NROWS + (h+8))*RLEN + 448;
    for (int idx = threadIdx.x; idx < 4096; idx += 256){
        int w = idx >> 5, c2 = (idx & 31)*2;
        float v0 = sx[c2*129 + w] * sm[w];
        float v1 = sx[(c2+1)*129 + w] * sm[w];
        u32 hw, lw; split2(v0, v1, hw, lw);
        size_t e = base + (size_t)w*64 + c2;
        *(u32*)(g_xA_h + e) = hw;
        *(u32*)(g_xA_l + e) = lw;
    }
}

// ---------------- weight prep: split B tiles [tile][o][c] -------------------
__global__ void wprep_kernel(const float* __restrict__ kern, const float* __restrict__ cow)
{
    int i = blockIdx.x*256 + threadIdx.x;
    if (i < 4*27*4096){
        int tile = i >> 12, e = i & 4095, o = e >> 6, c = e & 63;
        int b = tile / 27, r = tile % 27, tap = r / 3, m = r % 3;
        float v = kern[(((b*3 + m)*64 + o)*64 + c)*9 + tap];
        __nv_bfloat16 hi = __float2bfloat16(v);
        g_wb_h[i] = hi;
        g_wb_l[i] = __float2bfloat16(v - __bfloat162float(hi));
    }
    if (i < 36*4096){
        int tile = i >> 12, e = i & 4095, o = e >> 6, c = e & 63;
        int tap = tile / 4, ch = tile % 4;
        float v = cow[(o*256 + ch*64 + c)*9 + tap];
        __nv_bfloat16 hi = __float2bfloat16(v);
        g_wo_h[i] = hi;
        g_wo_l[i] = __float2bfloat16(v - __bfloat162float(hi));
    }
}

// ---------------- MMA mainloop: 256 threads, 3-stage ring, 1 sync/stage -----
// Stage buffer (bytes): A hi @0 (18432), A lo @18432, B hi @36864 (9216), B lo @46080.
// 3 buffers = 165888 bytes total.
template<int NS, int NCH>
__device__ __forceinline__ void mma_mainloop(
    const __nv_bfloat16* __restrict__ xah, const __nv_bfloat16* __restrict__ xal,
    const __nv_bfloat16* __restrict__ wth, const __nv_bfloat16* __restrict__ wtl,
    int d, int h, float acc[8][4])
{
    extern __shared__ __align__(16) unsigned char smraw[];
    u32 sm0 = s2u(smraw);
    const int tid = threadIdx.x, lane = tid & 31, wid = tid >> 5;

    #pragma unroll
    for (int i = 0; i < 8; i++)
        #pragma unroll
        for (int j = 0; j < 4; j++) acc[i][j] = 0.f;

    auto issue = [&](int s, int buf){
        int tap = s / NCH, ch = s - tap*NCH;
        int dh = (tap/3 - 1)*d, dw = (tap%3 - 1)*d;
        size_t arow = ((size_t)ch*NROWS + (h + 8 + dh))*RLEN + 448 + (long)dw*64;
        u32 abase = sm0 + (u32)buf*BUFSZ;
        #pragma unroll
        for (int t = 0; t < 4; t++){
            int idx = tid + t*256; int w = idx >> 3, c16 = idx & 7;
            size_t off = arow + (size_t)w*64 + c16*8;
            u32 dst = abase + (u32)(w*144 + c16*16);
            CP16(dst,        xah + off);
            CP16(dst + A_LO, xal + off);
        }
        u32 bbase = abase + B_OFF;
        const __nv_bfloat16* wsh = wth + (size_t)s*4096;
        const __nv_bfloat16* wsl = wtl + (size_t)s*4096;
        #pragma unroll
        for (int t = 0; t < 2; t++){
            int idx = tid + t*256; int o = idx >> 3, c16 = idx & 7;
            u32 dst = bbase + (u32)(o*144 + c16*16);
            CP16(dst,        wsh + o*64 + c16*8);
            CP16(dst + B_LO, wsl + o*64 + c16*8);
        }
    };

    issue(0, 0); CP_COMMIT();
    issue(1, 1); CP_COMMIT();

    const u32 a_lane = (u32)((wid*16 + (lane & 15))*144 + (lane >> 4)*16);
    const int br = lane & 7, bq = lane >> 3;
    const u32 b_lane0 = (u32)((br + (bq >> 1)*8)*144 + (bq & 1)*16);

    int buf = 0;
    for (int s = 0; s < NS; s++){
        CP_WAIT1();
        __syncthreads();
        u32 ab = sm0 + (u32)buf*BUFSZ + a_lane;
        u32 bb = sm0 + (u32)buf*BUFSZ + B_OFF + b_lane0;

        // hoist all A fragments for this stage (8 independent LDSM)
        u32 ah[4][4], al[4][4];
        #pragma unroll
        for (int ks = 0; ks < 4; ks++){
            LDX4(ah[ks], ab + ks*32);
            LDX4(al[ks], ab + ks*32 + A_LO);
        }
        #pragma unroll
        for (int np = 0; np < 4; np++){
            #pragma unroll
            for (int ks = 0; ks < 4; ks++){
                u32 bh[4], bl[4];
                u32 ba = bb + (u32)(np*16*144) + ks*32;
                LDX4(bh, ba);
                LDX4(bl, ba + B_LO);
                MMA(acc[2*np],   ah[ks], bh[0], bh[1]);
                MMA(acc[2*np],   ah[ks], bl[0], bl[1]);
                MMA(acc[2*np],   al[ks], bh[0], bh[1]);
                MMA(acc[2*np+1], ah[ks], bh[2], bh[3]);
                MMA(acc[2*np+1], ah[ks], bl[2], bl[3]);
                MMA(acc[2*np+1], al[ks], bh[2], bh[3]);
            }
        }
        // fill buffer (s+2)%3 — distinct from buffers in use at stages s, s+1
        if (s + 2 < NS){
            int nb = buf + 2; if (nb >= 3) nb -= 3;
            issue(s + 2, nb);
        }
        CP_COMMIT();
        if (++buf == 3) buf = 0;
    }
}

// ---------------- branch conv: writes split cat tiles ------------------------
__global__ void __launch_bounds__(256, 1)
branch_mma()
{
    int bx = blockIdx.x;                  // h | di<<7 | b<<9
    int h = bx & 127, di = (bx >> 7) & 3, b = bx >> 9;
    int d = 2*di + 1;

    float acc[8][4];
    mma_mainloop<27, 3>(g_xA_h + (size_t)(b*3)*NROWS*RLEN,
                        g_xA_l + (size_t)(b*3)*NROWS*RLEN,
                        g_wb_h + (size_t)b*27*4096,
                        g_wb_l + (size_t)b*27*4096, d, h, acc);

    const int lane = threadIdx.x & 31, wid = threadIdx.x >> 5;
    const int w0 = wid*16, g = lane >> 2, tig = lane & 3;
    size_t cb = ((size_t)(b*4 + di)*NROWS + (h + 8))*RLEN + 448;
    #pragma unroll
    for (int nt = 0; nt < 8; nt++){
        int o = nt*8 + 2*tig;
        u32 hw, lw;
        split2(acc[nt][0], acc[nt][1], hw, lw);
        size_t e0 = cb + (size_t)(w0 + g)*64 + o;
        *(u32*)(g_cA_h + e0) = hw; *(u32*)(g_cA_l + e0) = lw;
        split2(acc[nt][2], acc[nt][3], hw, lw);
        size_t e1 = cb + (size_t)(w0 + g + 8)*64 + o;
        *(u32*)(g_cA_h + e1) = hw; *(u32*)(g_cA_l + e1) = lw;
    }
}

// ---------------- out conv + bias + BN + ReLU --------------------------------
__global__ void __launch_bounds__(256, 1)
out_mma(const float* __restrict__ cob, const float* __restrict__ gamma,
        const float* __restrict__ beta, const float* __restrict__ mean,
        const float* __restrict__ var, float* __restrict__ out)
{
    __shared__ float sInv[64], sAdd[64], sBias[64];
    int bx = blockIdx.x;                  // h | b<<7
    int h = bx & 127, b = bx >> 7;
    if (threadIdx.x < 64){
        int o = threadIdx.x;
        float inv = gamma[o] * rsqrtf(var[o] + 1e-5f);
        sInv[o] = inv; sAdd[o] = beta[o] - mean[o]*inv; sBias[o] = cob[o];
    }

    float acc[8][4];
    mma_mainloop<36, 4>(g_cA_h + (size_t)(b*4)*NROWS*RLEN,
                        g_cA_l + (size_t)(b*4)*NROWS*RLEN,
                        g_wo_h, g_wo_l, 1, h, acc);

    const int lane = threadIdx.x & 31, wid = threadIdx.x >> 5;
    const int w0 = wid*16, g = lane >> 2, tig = lane & 3;
    #pragma unroll
    for (int nt = 0; nt < 8; nt++){
        int o = nt*8 + 2*tig;
        float i0 = sInv[o], a0 = sAdd[o], c0 = sBias[o];
        float i1 = sInv[o+1], a1 = sAdd[o+1], c1 = sBias[o+1];
        float* p0 = out + ((size_t)(b*64 + o))*HW + h*128;
        float* p1 = p0 + HW;
        p0[w0 + g]     = fmaxf((acc[nt][0] + c0)*i0 + a0, 0.f);
        p1[w0 + g]     = fmaxf((acc[nt][1] + c1)*i1 + a1, 0.f);
        p0[w0 + g + 8] = fmaxf((acc[nt][2] + c0)*i0 + a0, 0.f);
        p1[w0 + g + 8] = fmaxf((acc[nt][3] + c1)*i1 + a1, 0.f);
    }
}

// ---------------- host --------------------------------------------------------
extern "C" void kernel_launch(void* const* d_in, const int* in_sizes, int n_in,
                              void* d_out, int out_size)
{
    const float* x     = (const float*)d_in[0];
    const float* kern  = (const float*)d_in[1];
    const float* mw    = (const float*)d_in[2];
    const float* mb    = (const float*)d_in[3];
    const float* cow   = (const float*)d_in[4];
    const float* cob   = (const float*)d_in[5];
    const float* gamma = (const float*)d_in[6];
    const float* beta  = (const float*)d_in[7];
    const float* mean  = (const float*)d_in[8];
    const float* var   = (const float*)d_in[9];
    float* out   = (float*)d_out;
    float* masks = out + 4*64*HW;

    const int SMEM = 3 * 55296;   // 165888
    cudaFuncSetAttribute(branch_mma, cudaFuncAttributeMaxDynamicSharedMemorySize, SMEM);
    cudaFuncSetAttribute(out_mma,    cudaFuncAttributeMaxDynamicSharedMemorySize, SMEM);

    mask_kernel<<<256, 256>>>(x, mw, mb, masks);
    xmT_kernel<<<1536, 256>>>(x, masks);
    wprep_kernel<<<1728, 256>>>(kern, cow);
    branch_mma<<<2048, 256, SMEM>>>();
    out_mma<<<512, 256, SMEM>>>(cob, gamma, beta, mean, var, out);
}

// round 11
// speedup vs baseline: 1.3571x; 1.1170x over previous
#include <cuda_runtime.h>
#include <cuda_bf16.h>
#include <stdint.h>
#include <math.h>

#define HW 16384
#define RLEN 9088         // padded row: 448 + 128*64 + 448 elems
#define NROWS 144         // h = -8 .. 135
// Stage buffer (bytes): A hi @0 (9216), A lo @9216, B hi @18432 (9216), B lo @27648
#define A_LO  9216u
#define B_OFF 18432u
#define B_LO  9216u
#define BUFSZ 36864u      // one stage; 2 stages = 73728 -> 3 CTAs/SM
typedef unsigned u32; typedef unsigned long long u64;

// ---------------- device scratch (zero-initialized; pads never written) ----
__device__ __align__(256) __nv_bfloat16 g_xA_h[12 * NROWS * RLEN];
__device__ __align__(256) __nv_bfloat16 g_xA_l[12 * NROWS * RLEN];
__device__ __align__(256) __nv_bfloat16 g_cA_h[16 * NROWS * RLEN];
__device__ __align__(256) __nv_bfloat16 g_cA_l[16 * NROWS * RLEN];
__device__ __align__(256) __nv_bfloat16 g_wb_h[4 * 27 * 4096];
__device__ __align__(256) __nv_bfloat16 g_wb_l[4 * 27 * 4096];
__device__ __align__(256) __nv_bfloat16 g_wo_h[36 * 4096];
__device__ __align__(256) __nv_bfloat16 g_wo_l[36 * 4096];

// ---------------- PTX helpers ----------------------------------------------
__device__ __forceinline__ u32 s2u(const void* p){
    u32 a; asm("{ .reg .u64 t; cvta.to.shared.u64 t, %1; cvt.u32.u64 %0, t; }"
               : "=r"(a) : "l"(p)); return a;
}
#define CP16(dst, src) \
    asm volatile("cp.async.cg.shared.global [%0], [%1], 16;" :: "r"(dst), "l"(src) : "memory")
#define CP_COMMIT() asm volatile("cp.async.commit_group;" ::: "memory")
#define CP_WAIT1()  asm volatile("cp.async.wait_group 1;" ::: "memory")
#define LDX4(r, a) \
    asm volatile("ldmatrix.sync.aligned.m8n8.x4.shared.b16 {%0,%1,%2,%3}, [%4];" \
        : "=r"((r)[0]), "=r"((r)[1]), "=r"((r)[2]), "=r"((r)[3]) : "r"(a))
#define MMA(d, a, b0, b1) \
    asm("mma.sync.aligned.m16n8k16.row.col.f32.bf16.bf16.f32 " \
        "{%0,%1,%2,%3},{%4,%5,%6,%7},{%8,%9},{%0,%1,%2,%3};" \
        : "+f"((d)[0]), "+f"((d)[1]), "+f"((d)[2]), "+f"((d)[3]) \
        : "r"((a)[0]), "r"((a)[1]), "r"((a)[2]), "r"((a)[3]), "r"(b0), "r"(b1))

__device__ __forceinline__ void split2(float v0, float v1, u32& hw, u32& lw){
    __nv_bfloat16 h0 = __float2bfloat16(v0);
    __nv_bfloat16 h1 = __float2bfloat16(v1);
    __nv_bfloat16 l0 = __float2bfloat16(v0 - __bfloat162float(h0));
    __nv_bfloat16 l1 = __float2bfloat16(v1 - __bfloat162float(h1));
    hw = (u32)*(unsigned short*)&h0 | ((u32)*(unsigned short*)&h1 << 16);
    lw = (u32)*(unsigned short*)&l0 | ((u32)*(unsigned short*)&l1 << 16);
}

// ---------------- stage 1: mask conv + softmax ------------------------------
__global__ void mask_kernel(const float* __restrict__ x, const float* __restrict__ mw,
                            const float* __restrict__ mb, float* __restrict__ masks)
{
    __shared__ float s_mw[3*64*9];
    for (int i = threadIdx.x; i < 3*64*9; i += 256) s_mw[i] = mw[i];
    __syncthreads();
    int gid = blockIdx.x*256 + threadIdx.x;
    int b = gid >> 14, pid = gid & (HW-1), h = pid >> 7, w = pid & 127;
    float a0 = mb[0], a1 = mb[1], a2 = mb[2];
    const float* xb = x + b*64*HW;
    for (int c = 0; c < 64; c++){
        const float* xc = xb + c*HW; const float* wc = s_mw + c*9;
        #pragma unroll
        for (int kh = 0; kh < 3; kh++){
            int hh = h + kh - 1; if ((unsigned)hh >= 128u) continue;
            #pragma unroll
            for (int kw = 0; kw < 3; kw++){
                int ww = w + kw - 1; if ((unsigned)ww >= 128u) continue;
                float v = xc[hh*128 + ww]; int t = kh*3 + kw;
                a0 = fmaf(v, wc[t], a0); a1 = fmaf(v, wc[576+t], a1); a2 = fmaf(v, wc[1152+t], a2);
            }
        }
    }
    float mx = fmaxf(a0, fmaxf(a1, a2));
    float e0 = expf(a0-mx), e1 = expf(a1-mx), e2 = expf(a2-mx);
    float inv = 1.f/(e0+e1+e2);
    masks[(b*3+0)*HW+pid] = e0*inv; masks[(b*3+1)*HW+pid] = e1*inv; masks[(b*3+2)*HW+pid] = e2*inv;
}

// ---------------- stage 2: transpose + split xm into padded layout ----------
__global__ void xmT_kernel(const float* __restrict__ x, const float* __restrict__ masks)
{
    __shared__ float sx[64*129];
    __shared__ float sm[128];
    int bx = blockIdx.x;                 // (bm<<7)|h
    int h = bx & 127, bm = bx >> 7, m = bm % 3, b = bm / 3;
    for (int idx = threadIdx.x; idx < 8192; idx += 256){
        int c = idx >> 7, w = idx & 127;
        sx[c*129 + w] = x[(b*64 + c)*HW + h*128 + w];
    }
    if (threadIdx.x < 128) sm[threadIdx.x] = masks[bm*HW + h*128 + threadIdx.x];
    __syncthreads();
    size_t base = ((size_t)bm*NROWS + (h+8))*RLEN + 448;
    for (int idx = threadIdx.x; idx < 4096; idx += 256){
        int w = idx >> 5, c2 = (idx & 31)*2;
        float v0 = sx[c2*129 + w] * sm[w];
        float v1 = sx[(c2+1)*129 + w] * sm[w];
        u32 hw, lw; split2(v0, v1, hw, lw);
        size_t e = base + (size_t)w*64 + c2;
        *(u32*)(g_xA_h + e) = hw;
        *(u32*)(g_xA_l + e) = lw;
    }
}

// ---------------- weight prep: split B tiles [tile][o][c] -------------------
__global__ void wprep_kernel(const float* __restrict__ kern, const float* __restrict__ cow)
{
    int i = blockIdx.x*256 + threadIdx.x;
    if (i < 4*27*4096){
        int tile = i >> 12, e = i & 4095, o = e >> 6, c = e & 63;
        int b = tile / 27, r = tile % 27, tap = r / 3, m = r % 3;
        float v = kern[(((b*3 + m)*64 + o)*64 + c)*9 + tap];
        __nv_bfloat16 hi = __float2bfloat16(v);
        g_wb_h[i] = hi;
        g_wb_l[i] = __float2bfloat16(v - __bfloat162float(hi));
    }
    if (i < 36*4096){
        int tile = i >> 12, e = i & 4095, o = e >> 6, c = e & 63;
        int tap = tile / 4, ch = tile % 4;
        float v = cow[(o*256 + ch*64 + c)*9 + tap];
        __nv_bfloat16 hi = __float2bfloat16(v);
        g_wo_h[i] = hi;
        g_wo_l[i] = __float2bfloat16(v - __bfloat162float(hi));
    }
}

// ---------------- MMA mainloop: 128 threads, M=64 tile, double-buffered -----
// Each of 4 warps computes m16 x n64 (8 n-tiles). R8 structure, 3 CTAs/SM.
// mh selects which 64-px half of the row this CTA computes.
template<int NS, int NCH>
__device__ __forceinline__ void mma_mainloop(
    const __nv_bfloat16* __restrict__ xah, const __nv_bfloat16* __restrict__ xal,
    const __nv_bfloat16* __restrict__ wth, const __nv_bfloat16* __restrict__ wtl,
    int d, int h, int mh, float acc[8][4])
{
    extern __shared__ __align__(16) unsigned char smraw[];
    u32 sm0 = s2u(smraw);
    const int tid = threadIdx.x, lane = tid & 31, wid = tid >> 5;

    #pragma unroll
    for (int i = 0; i < 8; i++)
        #pragma unroll
        for (int j = 0; j < 4; j++) acc[i][j] = 0.f;

    auto issue = [&](int s, int buf){
        int tap = s / NCH, ch = s - tap*NCH;
        int dh = (tap/3 - 1)*d, dw = (tap%3 - 1)*d;
        size_t arow = ((size_t)ch*NROWS + (h + 8 + dh))*RLEN + 448
                    + ((long)mh*64 + dw)*64;
        u32 abase = sm0 + (u32)buf*BUFSZ;
        #pragma unroll
        for (int t = 0; t < 4; t++){
            int idx = tid + t*128; int w = idx >> 3, c16 = idx & 7;
            size_t off = arow + (size_t)w*64 + c16*8;
            u32 dst = abase + (u32)(w*144 + c16*16);
            CP16(dst,        xah + off);
            CP16(dst + A_LO, xal + off);
        }
        u32 bbase = abase + B_OFF;
        const __nv_bfloat16* wsh = wth + (size_t)s*4096;
        const __nv_bfloat16* wsl = wtl + (size_t)s*4096;
        #pragma unroll
        for (int t = 0; t < 4; t++){
            int idx = tid + t*128; int o = idx >> 3, c16 = idx & 7;
            u32 dst = bbase + (u32)(o*144 + c16*16);
            CP16(dst,        wsh + o*64 + c16*8);
            CP16(dst + B_LO, wsl + o*64 + c16*8);
        }
    };

    issue(0, 0); CP_COMMIT();
    issue(1, 1); CP_COMMIT();

    const u32 a_lane = (u32)((wid*16 + (lane & 15))*144 + (lane >> 4)*16);
    const int br = lane & 7, bq = lane >> 3;
    const u32 b_lane0 = (u32)((br + (bq >> 1)*8)*144 + (bq & 1)*16);

    for (int s = 0; s < NS; s++){
        int buf = s & 1;
        CP_WAIT1();
        __syncthreads();
        u32 ab = sm0 + (u32)buf*BUFSZ + a_lane;
        u32 bb = sm0 + (u32)buf*BUFSZ + B_OFF + b_lane0;
        #pragma unroll
        for (int ks = 0; ks < 4; ks++){
            u32 ah[4], al[4];
            LDX4(ah, ab + ks*32);
            LDX4(al, ab + ks*32 + A_LO);
            #pragma unroll
            for (int np = 0; np < 4; np++){
                u32 bh[4], bl[4];
                u32 ba = bb + (u32)(np*16*144) + ks*32;
                LDX4(bh, ba);
                LDX4(bl, ba + B_LO);
                MMA(acc[2*np],   ah, bh[0], bh[1]);
                MMA(acc[2*np],   ah, bl[0], bl[1]);
                MMA(acc[2*np],   al, bh[0], bh[1]);
                MMA(acc[2*np+1], ah, bh[2], bh[3]);
                MMA(acc[2*np+1], ah, bl[2], bl[3]);
                MMA(acc[2*np+1], al, bh[2], bh[3]);
            }
        }
        __syncthreads();
        if (s + 2 < NS) issue(s + 2, buf);
        CP_COMMIT();
    }
}

// ---------------- branch conv: writes split cat tiles ------------------------
__global__ void __launch_bounds__(128, 3)
branch_mma()
{
    int bx = blockIdx.x;                  // mh | h<<1 | di<<8 | b<<10
    int mh = bx & 1, h = (bx >> 1) & 127, di = (bx >> 8) & 3, b = bx >> 10;
    int d = 2*di + 1;

    float acc[8][4];
    mma_mainloop<27, 3>(g_xA_h + (size_t)(b*3)*NROWS*RLEN,
                        g_xA_l + (size_t)(b*3)*NROWS*RLEN,
                        g_wb_h + (size_t)b*27*4096,
                        g_wb_l + (size_t)b*27*4096, d, h, mh, acc);

    const int lane = threadIdx.x & 31, wid = threadIdx.x >> 5;
    const int w0 = mh*64 + wid*16, g = lane >> 2, tig = lane & 3;
    size_t cb = ((size_t)(b*4 + di)*NROWS + (h + 8))*RLEN + 448;
    #pragma unroll
    for (int nt = 0; nt < 8; nt++){
        int o = nt*8 + 2*tig;
        u32 hw, lw;
        split2(acc[nt][0], acc[nt][1], hw, lw);
        size_t e0 = cb + (size_t)(w0 + g)*64 + o;
        *(u32*)(g_cA_h + e0) = hw; *(u32*)(g_cA_l + e0) = lw;
        split2(acc[nt][2], acc[nt][3], hw, lw);
        size_t e1 = cb + (size_t)(w0 + g + 8)*64 + o;
        *(u32*)(g_cA_h + e1) = hw; *(u32*)(g_cA_l + e1) = lw;
    }
}

// ---------------- out conv + bias + BN + ReLU --------------------------------
__global__ void __launch_bounds__(128, 3)
out_mma(const float* __restrict__ cob, const float* __restrict__ gamma,
        const float* __restrict__ beta, const float* __restrict__ mean,
        const float* __restrict__ var, float* __restrict__ out)
{
    __shared__ float sInv[64], sAdd[64], sBias[64];
    int bx = blockIdx.x;                  // mh | h<<1 | b<<8
    int mh = bx & 1, h = (bx >> 1) & 127, b = bx >> 8;
    if (threadIdx.x < 64){
        int o = threadIdx.x;
        float inv = gamma[o] * rsqrtf(var[o] + 1e-5f);
        sInv[o] = inv; sAdd[o] = beta[o] - mean[o]*inv; sBias[o] = cob[o];
    }

    float acc[8][4];
    mma_mainloop<36, 4>(g_cA_h + (size_t)(b*4)*NROWS*RLEN,
                        g_cA_l + (size_t)(b*4)*NROWS*RLEN,
                        g_wo_h, g_wo_l, 1, h, mh, acc);

    const int lane = threadIdx.x & 31, wid = threadIdx.x >> 5;
    const int w0 = mh*64 + wid*16, g = lane >> 2, tig = lane & 3;
    #pragma unroll
    for (int nt = 0; nt < 8; nt++){
        int o = nt*8 + 2*tig;
        float i0 = sInv[o], a0 = sAdd[o], c0 = sBias[o];
        float i1 = sInv[o+1], a1 = sAdd[o+1], c1 = sBias[o+1];
        float* p0 = out + ((size_t)(b*64 + o))*HW + h*128;
        float* p1 = p0 + HW;
        p0[w0 + g]     = fmaxf((acc[nt][0] + c0)*i0 + a0, 0.f);
        p1[w0 + g]     = fmaxf((acc[nt][1] + c1)*i1 + a1, 0.f);
        p0[w0 + g + 8] = fmaxf((acc[nt][2] + c0)*i0 + a0, 0.f);
        p1[w0 + g + 8] = fmaxf((acc[nt][3] + c1)*i1 + a1, 0.f);
    }
}

// ---------------- host --------------------------------------------------------
extern "C" void kernel_launch(void* const* d_in, const int* in_sizes, int n_in,
                              void* d_out, int out_size)
{
    const float* x     = (const float*)d_in[0];
    const float* kern  = (const float*)d_in[1];
    const float* mw    = (const float*)d_in[2];
    const float* mb    = (const float*)d_in[3];
    const float* cow   = (const float*)d_in[4];
    const float* cob   = (const float*)d_in[5];
    const float* gamma = (const float*)d_in[6];
    const float* beta  = (const float*)d_in[7];
    const float* mean  = (const float*)d_in[8];
    const float* var   = (const float*)d_in[9];
    float* out   = (float*)d_out;
    float* masks = out + 4*64*HW;

    const int SMEM = 2 * 36864;   // 73728 -> 3 CTAs/SM
    cudaFuncSetAttribute(branch_mma, cudaFuncAttributeMaxDynamicSharedMemorySize, SMEM);
    cudaFuncSetAttribute(out_mma,    cudaFuncAttributeMaxDynamicSharedMemorySize, SMEM);

    mask_kernel<<<256, 256>>>(x, mw, mb, masks);
    xmT_kernel<<<1536, 256>>>(x, masks);
    wprep_kernel<<<1728, 256>>>(kern, cow);
    branch_mma<<<4096, 128, SMEM>>>();
    out_mma<<<1024, 128, SMEM>>>(cob, gamma, beta, mean, var, out);
}

// round 12
// speedup vs baseline: 1.6837x; 1.2407x over previous
#include <cuda_runtime.h>
#include <cuda_fp16.h>
#include <stdint.h>
#include <math.h>

#define HW 16384
#define RLEN 9088         // padded row: 448 + 128*64 + 448 elems
#define NROWS 144         // h = -8 .. 135
// Stage buffer (bytes): A hi @0 (18432), A lo @18432, B hi @36864 (9216)
#define A_LO  18432u
#define B_OFF 36864u
#define BUFSZ 46080u      // one stage; 2 stages = 92160 -> 2 CTAs/SM
typedef unsigned u32; typedef unsigned long long u64;

// ---------------- device scratch (zero-initialized; pads never written) ----
__device__ __align__(256) __half g_xA_h[12 * NROWS * RLEN];
__device__ __align__(256) __half g_xA_l[12 * NROWS * RLEN];
__device__ __align__(256) __half g_cA_h[16 * NROWS * RLEN];
__device__ __align__(256) __half g_cA_l[16 * NROWS * RLEN];
__device__ __align__(256) __half g_wb_h[4 * 27 * 4096];
__device__ __align__(256) __half g_wo_h[36 * 4096];

// ---------------- PTX helpers ----------------------------------------------
__device__ __forceinline__ u32 s2u(const void* p){
    u32 a; asm("{ .reg .u64 t; cvta.to.shared.u64 t, %1; cvt.u32.u64 %0, t; }"
               : "=r"(a) : "l"(p)); return a;
}
#define CP16(dst, src) \
    asm volatile("cp.async.cg.shared.global [%0], [%1], 16;" :: "r"(dst), "l"(src) : "memory")
#define CP_COMMIT() asm volatile("cp.async.commit_group;" ::: "memory")
#define CP_WAIT1()  asm volatile("cp.async.wait_group 1;" ::: "memory")
#define LDX4(r, a) \
    asm volatile("ldmatrix.sync.aligned.m8n8.x4.shared.b16 {%0,%1,%2,%3}, [%4];" \
        : "=r"((r)[0]), "=r"((r)[1]), "=r"((r)[2]), "=r"((r)[3]) : "r"(a))
#define MMA(d, a, b0, b1) \
    asm("mma.sync.aligned.m16n8k16.row.col.f32.f16.f16.f32 " \
        "{%0,%1,%2,%3},{%4,%5,%6,%7},{%8,%9},{%0,%1,%2,%3};" \
        : "+f"((d)[0]), "+f"((d)[1]), "+f"((d)[2]), "+f"((d)[3]) \
        : "r"((a)[0]), "r"((a)[1]), "r"((a)[2]), "r"((a)[3]), "r"(b0), "r"(b1))

__device__ __forceinline__ void split2h(float v0, float v1, u32& hw, u32& lw){
    __half h0 = __float2half_rn(v0);
    __half h1 = __float2half_rn(v1);
    __half l0 = __float2half_rn(v0 - __half2float(h0));
    __half l1 = __float2half_rn(v1 - __half2float(h1));
    hw = (u32)*(unsigned short*)&h0 | ((u32)*(unsigned short*)&h1 << 16);
    lw = (u32)*(unsigned short*)&l0 | ((u32)*(unsigned short*)&l1 << 16);
}

// ---------------- stage 1: mask conv + softmax ------------------------------
__global__ void mask_kernel(const float* __restrict__ x, const float* __restrict__ mw,
                            const float* __restrict__ mb, float* __restrict__ masks)
{
    __shared__ float s_mw[3*64*9];
    for (int i = threadIdx.x; i < 3*64*9; i += 256) s_mw[i] = mw[i];
    __syncthreads();
    int gid = blockIdx.x*256 + threadIdx.x;
    int b = gid >> 14, pid = gid & (HW-1), h = pid >> 7, w = pid & 127;
    float a0 = mb[0], a1 = mb[1], a2 = mb[2];
    const float* xb = x + b*64*HW;
    for (int c = 0; c < 64; c++){
        const float* xc = xb + c*HW; const float* wc = s_mw + c*9;
        #pragma unroll
        for (int kh = 0; kh < 3; kh++){
            int hh = h + kh - 1; if ((unsigned)hh >= 128u) continue;
            #pragma unroll
            for (int kw = 0; kw < 3; kw++){
                int ww = w + kw - 1; if ((unsigned)ww >= 128u) continue;
                float v = xc[hh*128 + ww]; int t = kh*3 + kw;
                a0 = fmaf(v, wc[t], a0); a1 = fmaf(v, wc[576+t], a1); a2 = fmaf(v, wc[1152+t], a2);
            }
        }
    }
    float mx = fmaxf(a0, fmaxf(a1, a2));
    float e0 = expf(a0-mx), e1 = expf(a1-mx), e2 = expf(a2-mx);
    float inv = 1.f/(e0+e1+e2);
    masks[(b*3+0)*HW+pid] = e0*inv; masks[(b*3+1)*HW+pid] = e1*inv; masks[(b*3+2)*HW+pid] = e2*inv;
}

// ---------------- stage 2: transpose + split xm into padded layout ----------
__global__ void xmT_kernel(const float* __restrict__ x, const float* __restrict__ masks)
{
    __shared__ float sx[64*129];
    __shared__ float sm[128];
    int bx = blockIdx.x;                 // (bm<<7)|h
    int h = bx & 127, bm = bx >> 7, m = bm % 3, b = bm / 3;
    for (int idx = threadIdx.x; idx < 8192; idx += 256){
        int c = idx >> 7, w = idx & 127;
        sx[c*129 + w] = x[(b*64 + c)*HW + h*128 + w];
    }
    if (threadIdx.x < 128) sm[threadIdx.x] = masks[bm*HW + h*128 + threadIdx.x];
    __syncthreads();
    size_t base = ((size_t)bm*NROWS + (h+8))*RLEN + 448;
    for (int idx = threadIdx.x; idx < 4096; idx += 256){
        int w = idx >> 5, c2 = (idx & 31)*2;
        float v0 = sx[c2*129 + w] * sm[w];
        float v1 = sx[(c2+1)*129 + w] * sm[w];
        u32 hw, lw; split2h(v0, v1, hw, lw);
        size_t e = base + (size_t)w*64 + c2;
        *(u32*)(g_xA_h + e) = hw;
        *(u32*)(g_xA_l + e) = lw;
    }
}

// ---------------- weight prep: fp16 B tiles [tile][o][c] --------------------
__global__ void wprep_kernel(const float* __restrict__ kern, const float* __restrict__ cow)
{
    int i = blockIdx.x*256 + threadIdx.x;
    if (i < 4*27*4096){
        int tile = i >> 12, e = i & 4095, o = e >> 6, c = e & 63;
        int b = tile / 27, r = tile % 27, tap = r / 3, m = r % 3;
        g_wb_h[i] = __float2half_rn(kern[(((b*3 + m)*64 + o)*64 + c)*9 + tap]);
    }
    if (i < 36*4096){
        int tile = i >> 12, e = i & 4095, o = e >> 6, c = e & 63;
        int tap = tile / 4, ch = tile % 4;
        g_wo_h[i] = __float2half_rn(cow[(o*256 + ch*64 + c)*9 + tap]);
    }
}

// ---------------- MMA mainloop: 256 threads, M=128, double-buffered ---------
// 2-MMA fp16 scheme: D += Ah*Bh + Al*Bh. B single fp16 tile.
template<int NS, int NCH>
__device__ __forceinline__ void mma_mainloop(
    const __half* __restrict__ xah, const __half* __restrict__ xal,
    const __half* __restrict__ wth,
    int d, int h, float acc[8][4])
{
    extern __shared__ __align__(16) unsigned char smraw[];
    u32 sm0 = s2u(smraw);
    const int tid = threadIdx.x, lane = tid & 31, wid = tid >> 5;

    #pragma unroll
    for (int i = 0; i < 8; i++)
        #pragma unroll
        for (int j = 0; j < 4; j++) acc[i][j] = 0.f;

    auto issue = [&](int s, int buf){
        int tap = s / NCH, ch = s - tap*NCH;
        int dh = (tap/3 - 1)*d, dw = (tap%3 - 1)*d;
        size_t arow = ((size_t)ch*NROWS + (h + 8 + dh))*RLEN + 448 + (long)dw*64;
        u32 abase = sm0 + (u32)buf*BUFSZ;
        #pragma unroll
        for (int t = 0; t < 4; t++){
            int idx = tid + t*256; int w = idx >> 3, c16 = idx & 7;
            size_t off = arow + (size_t)w*64 + c16*8;
            u32 dst = abase + (u32)(w*144 + c16*16);
            CP16(dst,        xah + off);
            CP16(dst + A_LO, xal + off);
        }
        u32 bbase = abase + B_OFF;
        const __half* wsh = wth + (size_t)s*4096;
        #pragma unroll
        for (int t = 0; t < 2; t++){
            int idx = tid + t*256; int o = idx >> 3, c16 = idx & 7;
            u32 dst = bbase + (u32)(o*144 + c16*16);
            CP16(dst, wsh + o*64 + c16*8);
        }
    };

    issue(0, 0); CP_COMMIT();
    issue(1, 1); CP_COMMIT();

    const u32 a_lane = (u32)((wid*16 + (lane & 15))*144 + (lane >> 4)*16);
    const int br = lane & 7, bq = lane >> 3;
    const u32 b_lane0 = (u32)((br + (bq >> 1)*8)*144 + (bq & 1)*16);

    for (int s = 0; s < NS; s++){
        int buf = s & 1;
        CP_WAIT1();
        __syncthreads();
        u32 ab = sm0 + (u32)buf*BUFSZ + a_lane;
        u32 bb = sm0 + (u32)buf*BUFSZ + B_OFF + b_lane0;
        #pragma unroll
        for (int ks = 0; ks < 4; ks++){
            u32 ah[4], al[4];
            LDX4(ah, ab + ks*32);
            LDX4(al, ab + ks*32 + A_LO);
            #pragma unroll
            for (int np = 0; np < 4; np++){
                u32 bh[4];
                LDX4(bh, bb + (u32)(np*16*144) + ks*32);
                MMA(acc[2*np],   ah, bh[0], bh[1]);
                MMA(acc[2*np],   al, bh[0], bh[1]);
                MMA(acc[2*np+1], ah, bh[2], bh[3]);
                MMA(acc[2*np+1], al, bh[2], bh[3]);
            }
        }
        __syncthreads();
        if (s + 2 < NS) issue(s + 2, buf);
        CP_COMMIT();
    }
}

// ---------------- branch conv: writes split cat tiles ------------------------
__global__ void __launch_bounds__(256, 2)
branch_mma()
{
    int bx = blockIdx.x;                  // h | di<<7 | b<<9
    int h = bx & 127, di = (bx >> 7) & 3, b = bx >> 9;
    int d = 2*di + 1;

    float acc[8][4];
    mma_mainloop<27, 3>(g_xA_h + (size_t)(b*3)*NROWS*RLEN,
                        g_xA_l + (size_t)(b*3)*NROWS*RLEN,
                        g_wb_h + (size_t)b*27*4096, d, h, acc);

    const int lane = threadIdx.x & 31, wid = threadIdx.x >> 5;
    const int w0 = wid*16, g = lane >> 2, tig = lane & 3;
    size_t cb = ((size_t)(b*4 + di)*NROWS + (h + 8))*RLEN + 448;
    #pragma unroll
    for (int nt = 0; nt < 8; nt++){
        int o = nt*8 + 2*tig;
        u32 hw, lw;
        split2h(acc[nt][0], acc[nt][1], hw, lw);
        size_t e0 = cb + (size_t)(w0 + g)*64 + o;
        *(u32*)(g_cA_h + e0) = hw; *(u32*)(g_cA_l + e0) = lw;
        split2h(acc[nt][2], acc[nt][3], hw, lw);
        size_t e1 = cb + (size_t)(w0 + g + 8)*64 + o;
        *(u32*)(g_cA_h + e1) = hw; *(u32*)(g_cA_l + e1) = lw;
    }
}

// ---------------- out conv + bias + BN + ReLU --------------------------------
__global__ void __launch_bounds__(256, 2)
out_mma(const float* __restrict__ cob, const float* __restrict__ gamma,
        const float* __restrict__ beta, const float* __restrict__ mean,
        const float* __restrict__ var, float* __restrict__ out)
{
    __shared__ float sInv[64], sAdd[64], sBias[64];
    int bx = blockIdx.x;                  // h | b<<7
    int h = bx & 127, b = bx >> 7;
    if (threadIdx.x < 64){
        int o = threadIdx.x;
        float inv = gamma[o] * rsqrtf(var[o] + 1e-5f);
        sInv[o] = inv; sAdd[o] = beta[o] - mean[o]*inv; sBias[o] = cob[o];
    }

    float acc[8][4];
    mma_mainloop<36, 4>(g_cA_h + (size_t)(b*4)*NROWS*RLEN,
                        g_cA_l + (size_t)(b*4)*NROWS*RLEN,
                        g_wo_h, 1, h, acc);

    const int lane = threadIdx.x & 31, wid = threadIdx.x >> 5;
    const int w0 = wid*16, g = lane >> 2, tig = lane & 3;
    #pragma unroll
    for (int nt = 0; nt < 8; nt++){
        int o = nt*8 + 2*tig;
        float i0 = sInv[o], a0 = sAdd[o], c0 = sBias[o];
        float i1 = sInv[o+1], a1 = sAdd[o+1], c1 = sBias[o+1];
        float* p0 = out + ((size_t)(b*64 + o))*HW + h*128;
        float* p1 = p0 + HW;
        p0[w0 + g]     = fmaxf((acc[nt][0] + c0)*i0 + a0, 0.f);
        p1[w0 + g]     = fmaxf((acc[nt][1] + c1)*i1 + a1, 0.f);
        p0[w0 + g + 8] = fmaxf((acc[nt][2] + c0)*i0 + a0, 0.f);
        p1[w0 + g + 8] = fmaxf((acc[nt][3] + c1)*i1 + a1, 0.f);
    }
}

// ---------------- host --------------------------------------------------------
extern "C" void kernel_launch(void* const* d_in, const int* in_sizes, int n_in,
                              void* d_out, int out_size)
{
    const float* x     = (const float*)d_in[0];
    const float* kern  = (const float*)d_in[1];
    const float* mw    = (const float*)d_in[2];
    const float* mb    = (const float*)d_in[3];
    const float* cow   = (const float*)d_in[4];
    const float* cob   = (const float*)d_in[5];
    const float* gamma = (const float*)d_in[6];
    const float* beta  = (const float*)d_in[7];
    const float* mean  = (const float*)d_in[8];
    const float* var   = (const float*)d_in[9];
    float* out   = (float*)d_out;
    float* masks = out + 4*64*HW;

    const int SMEM = 2 * 46080;   // 92160 -> 2 CTAs/SM
    cudaFuncSetAttribute(branch_mma, cudaFuncAttributeMaxDynamicSharedMemorySize, SMEM);
    cudaFuncSetAttribute(out_mma,    cudaFuncAttributeMaxDynamicSharedMemorySize, SMEM);

    mask_kernel<<<256, 256>>>(x, mw, mb, masks);
    xmT_kernel<<<1536, 256>>>(x, masks);
    wprep_kernel<<<1728, 256>>>(kern, cow);
    branch_mma<<<2048, 256, SMEM>>>();
    out_mma<<<512, 256, SMEM>>>(cob, gamma, beta, mean, var, out);
}

// round 13
// speedup vs baseline: 2.2515x; 1.3372x over previous
#include <cuda_runtime.h>
#include <cuda_fp16.h>
#include <stdint.h>
#include <math.h>

#define HW 16384
#define RLEN 9088         // padded row: 448 + 128*64 + 448 elems
#define NROWS 144         // h = -8 .. 135
typedef unsigned u32; typedef unsigned long long u64;

// ---------------- device scratch (zero-initialized; pads never written) ----
__device__ __align__(256) __half g_xA_h[12 * NROWS * RLEN];
__device__ __align__(256) __half g_cA_h[16 * NROWS * RLEN];
__device__ __align__(256) __half g_cA_l[16 * NROWS * RLEN];
__device__ __align__(256) __half g_wb_h[4 * 27 * 4096];
__device__ __align__(256) __half g_wo_h[36 * 4096];

// ---------------- PTX helpers ----------------------------------------------
__device__ __forceinline__ u32 s2u(const void* p){
    u32 a; asm("{ .reg .u64 t; cvta.to.shared.u64 t, %1; cvt.u32.u64 %0, t; }"
               : "=r"(a) : "l"(p)); return a;
}
#define CP16(dst, src) \
    asm volatile("cp.async.cg.shared.global [%0], [%1], 16;" :: "r"(dst), "l"(src) : "memory")
#define CP_COMMIT() asm volatile("cp.async.commit_group;" ::: "memory")
#define CP_WAIT1()  asm volatile("cp.async.wait_group 1;" ::: "memory")
#define LDX4(r, a) \
    asm volatile("ldmatrix.sync.aligned.m8n8.x4.shared.b16 {%0,%1,%2,%3}, [%4];" \
        : "=r"((r)[0]), "=r"((r)[1]), "=r"((r)[2]), "=r"((r)[3]) : "r"(a))
#define MMA(d, a, b0, b1) \
    asm("mma.sync.aligned.m16n8k16.row.col.f32.f16.f16.f32 " \
        "{%0,%1,%2,%3},{%4,%5,%6,%7},{%8,%9},{%0,%1,%2,%3};" \
        : "+f"((d)[0]), "+f"((d)[1]), "+f"((d)[2]), "+f"((d)[3]) \
        : "r"((a)[0]), "r"((a)[1]), "r"((a)[2]), "r"((a)[3]), "r"(b0), "r"(b1))

__device__ __forceinline__ void split2h(float v0, float v1, u32& hw, u32& lw){
    __half h0 = __float2half_rn(v0);
    __half h1 = __float2half_rn(v1);
    __half l0 = __float2half_rn(v0 - __half2float(h0));
    __half l1 = __float2half_rn(v1 - __half2float(h1));
    hw = (u32)*(unsigned short*)&h0 | ((u32)*(unsigned short*)&h1 << 16);
    lw = (u32)*(unsigned short*)&l0 | ((u32)*(unsigned short*)&l1 << 16);
}

// ---------------- stage 1: mask conv + softmax ------------------------------
__global__ void mask_kernel(const float* __restrict__ x, const float* __restrict__ mw,
                            const float* __restrict__ mb, float* __restrict__ masks)
{
    __shared__ float s_mw[3*64*9];
    for (int i = threadIdx.x; i < 3*64*9; i += 256) s_mw[i] = mw[i];
    __syncthreads();
    int gid = blockIdx.x*256 + threadIdx.x;
    int b = gid >> 14, pid = gid & (HW-1), h = pid >> 7, w = pid & 127;
    float a0 = mb[0], a1 = mb[1], a2 = mb[2];
    const float* xb = x + b*64*HW;
    for (int c = 0; c < 64; c++){
        const float* xc = xb + c*HW; const float* wc = s_mw + c*9;
        #pragma unroll
        for (int kh = 0; kh < 3; kh++){
            int hh = h + kh - 1; if ((unsigned)hh >= 128u) continue;
            #pragma unroll
            for (int kw = 0; kw < 3; kw++){
                int ww = w + kw - 1; if ((unsigned)ww >= 128u) continue;
                float v = xc[hh*128 + ww]; int t = kh*3 + kw;
                a0 = fmaf(v, wc[t], a0); a1 = fmaf(v, wc[576+t], a1); a2 = fmaf(v, wc[1152+t], a2);
            }
        }
    }
    float mx = fmaxf(a0, fmaxf(a1, a2));
    float e0 = expf(a0-mx), e1 = expf(a1-mx), e2 = expf(a2-mx);
    float inv = 1.f/(e0+e1+e2);
    masks[(b*3+0)*HW+pid] = e0*inv; masks[(b*3+1)*HW+pid] = e1*inv; masks[(b*3+2)*HW+pid] = e2*inv;
}

// ---------------- stage 2: transpose xm into padded fp16 layout (hi only) ---
__global__ void xmT_kernel(const float* __restrict__ x, const float* __restrict__ masks)
{
    __shared__ float sx[64*129];
    __shared__ float sm[128];
    int bx = blockIdx.x;                 // (bm<<7)|h
    int h = bx & 127, bm = bx >> 7, m = bm % 3, b = bm / 3;
    for (int idx = threadIdx.x; idx < 8192; idx += 256){
        int c = idx >> 7, w = idx & 127;
        sx[c*129 + w] = x[(b*64 + c)*HW + h*128 + w];
    }
    if (threadIdx.x < 128) sm[threadIdx.x] = masks[bm*HW + h*128 + threadIdx.x];
    __syncthreads();
    size_t base = ((size_t)bm*NROWS + (h+8))*RLEN + 448;
    for (int idx = threadIdx.x; idx < 4096; idx += 256){
        int w = idx >> 5, c2 = (idx & 31)*2;
        float v0 = sx[c2*129 + w] * sm[w];
        float v1 = sx[(c2+1)*129 + w] * sm[w];
        __half h0 = __float2half_rn(v0), h1 = __float2half_rn(v1);
        u32 hw = (u32)*(unsigned short*)&h0 | ((u32)*(unsigned short*)&h1 << 16);
        *(u32*)(g_xA_h + base + (size_t)w*64 + c2) = hw;
    }
}

// ---------------- weight prep: fp16 B tiles [tile][o][c] --------------------
__global__ void wprep_kernel(const float* __restrict__ kern, const float* __restrict__ cow)
{
    int i = blockIdx.x*256 + threadIdx.x;
    if (i < 4*27*4096){
        int tile = i >> 12, e = i & 4095, o = e >> 6, c = e & 63;
        int b = tile / 27, r = tile % 27, tap = r / 3, m = r % 3;
        g_wb_h[i] = __float2half_rn(kern[(((b*3 + m)*64 + o)*64 + c)*9 + tap]);
    }
    if (i < 36*4096){
        int tile = i >> 12, e = i & 4095, o = e >> 6, c = e & 63;
        int tap = tile / 4, ch = tile % 4;
        g_wo_h[i] = __float2half_rn(cow[(o*256 + ch*64 + c)*9 + tap]);
    }
}

// ---------------- MMA mainloop: 256 threads, M=128, double-buffered ---------
// SPLITA=false: A single fp16 (stage = A 18432 + B 9216 = 27648)
// SPLITA=true : A hi/lo     (stage = A 2*18432 + B 9216 = 46080)
template<int NS, int NCH, bool SPLITA>
__device__ __forceinline__ void mma_mainloop(
    const __half* __restrict__ xah, const __half* __restrict__ xal,
    const __half* __restrict__ wth,
    int d, int h, float acc[8][4])
{
    constexpr u32 A_LO  = 18432u;
    constexpr u32 B_OFF = SPLITA ? 36864u : 18432u;
    constexpr u32 BUFSZ = B_OFF + 9216u;

    extern __shared__ __align__(16) unsigned char smraw[];
    u32 sm0 = s2u(smraw);
    const int tid = threadIdx.x, lane = tid & 31, wid = tid >> 5;

    #pragma unroll
    for (int i = 0; i < 8; i++)
        #pragma unroll
        for (int j = 0; j < 4; j++) acc[i][j] = 0.f;

    auto issue = [&](int s, int buf){
        int tap = s / NCH, ch = s - tap*NCH;
        int dh = (tap/3 - 1)*d, dw = (tap%3 - 1)*d;
        size_t arow = ((size_t)ch*NROWS + (h + 8 + dh))*RLEN + 448 + (long)dw*64;
        u32 abase = sm0 + (u32)buf*BUFSZ;
        #pragma unroll
        for (int t = 0; t < 4; t++){
            int idx = tid + t*256; int w = idx >> 3, c16 = idx & 7;
            size_t off = arow + (size_t)w*64 + c16*8;
            u32 dst = abase + (u32)(w*144 + c16*16);
            CP16(dst, xah + off);
            if (SPLITA) CP16(dst + A_LO, xal + off);
        }
        u32 bbase = abase + B_OFF;
        const __half* wsh = wth + (size_t)s*4096;
        #pragma unroll
        for (int t = 0; t < 2; t++){
            int idx = tid + t*256; int o = idx >> 3, c16 = idx & 7;
            u32 dst = bbase + (u32)(o*144 + c16*16);
            CP16(dst, wsh + o*64 + c16*8);
        }
    };

    issue(0, 0); CP_COMMIT();
    issue(1, 1); CP_COMMIT();

    const u32 a_lane = (u32)((wid*16 + (lane & 15))*144 + (lane >> 4)*16);
    const int br = lane & 7, bq = lane >> 3;
    const u32 b_lane0 = (u32)((br + (bq >> 1)*8)*144 + (bq & 1)*16);

    for (int s = 0; s < NS; s++){
        int buf = s & 1;
        CP_WAIT1();
        __syncthreads();
        u32 ab = sm0 + (u32)buf*BUFSZ + a_lane;
        u32 bb = sm0 + (u32)buf*BUFSZ + B_OFF + b_lane0;
        #pragma unroll
        for (int ks = 0; ks < 4; ks++){
            u32 ah[4], al[4];
            LDX4(ah, ab + ks*32);
            if (SPLITA) LDX4(al, ab + ks*32 + A_LO);
            #pragma unroll
            for (int np = 0; np < 4; np++){
                u32 bh[4];
                LDX4(bh, bb + (u32)(np*16*144) + ks*32);
                MMA(acc[2*np],   ah, bh[0], bh[1]);
                if (SPLITA) MMA(acc[2*np], al, bh[0], bh[1]);
                MMA(acc[2*np+1], ah, bh[2], bh[3]);
                if (SPLITA) MMA(acc[2*np+1], al, bh[2], bh[3]);
            }
        }
        __syncthreads();
        if (s + 2 < NS) issue(s + 2, buf);
        CP_COMMIT();
    }
}

// ---------------- branch conv: pure fp16 A, writes split cat tiles -----------
__global__ void __launch_bounds__(256, 3)
branch_mma()
{
    int bx = blockIdx.x;                  // h | di<<7 | b<<9
    int h = bx & 127, di = (bx >> 7) & 3, b = bx >> 9;
    int d = 2*di + 1;

    float acc[8][4];
    mma_mainloop<27, 3, false>(g_xA_h + (size_t)(b*3)*NROWS*RLEN, nullptr,
                               g_wb_h + (size_t)b*27*4096, d, h, acc);

    const int lane = threadIdx.x & 31, wid = threadIdx.x >> 5;
    const int w0 = wid*16, g = lane >> 2, tig = lane & 3;
    size_t cb = ((size_t)(b*4 + di)*NROWS + (h + 8))*RLEN + 448;
    #pragma unroll
    for (int nt = 0; nt < 8; nt++){
        int o = nt*8 + 2*tig;
        u32 hw, lw;
        split2h(acc[nt][0], acc[nt][1], hw, lw);
        size_t e0 = cb + (size_t)(w0 + g)*64 + o;
        *(u32*)(g_cA_h + e0) = hw; *(u32*)(g_cA_l + e0) = lw;
        split2h(acc[nt][2], acc[nt][3], hw, lw);
        size_t e1 = cb + (size_t)(w0 + g + 8)*64 + o;
        *(u32*)(g_cA_h + e1) = hw; *(u32*)(g_cA_l + e1) = lw;
    }
}

// ---------------- out conv (A-split) + bias + BN + ReLU ----------------------
__global__ void __launch_bounds__(256, 2)
out_mma(const float* __restrict__ cob, const float* __restrict__ gamma,
        const float* __restrict__ beta, const float* __restrict__ mean,
        const float* __restrict__ var, float* __restrict__ out)
{
    __shared__ float sInv[64], sAdd[64], sBias[64];
    int bx = blockIdx.x;                  // h | b<<7
    int h = bx & 127, b = bx >> 7;
    if (threadIdx.x < 64){
        int o = threadIdx.x;
        float inv = gamma[o] * rsqrtf(var[o] + 1e-5f);
        sInv[o] = inv; sAdd[o] = beta[o] - mean[o]*inv; sBias[o] = cob[o];
    }

    float acc[8][4];
    mma_mainloop<36, 4, true>(g_cA_h + (size_t)(b*4)*NROWS*RLEN,
                              g_cA_l + (size_t)(b*4)*NROWS*RLEN,
                              g_wo_h, 1, h, acc);

    const int lane = threadIdx.x & 31, wid = threadIdx.x >> 5;
    const int w0 = wid*16, g = lane >> 2, tig = lane & 3;
    #pragma unroll
    for (int nt = 0; nt < 8; nt++){
        int o = nt*8 + 2*tig;
        float i0 = sInv[o], a0 = sAdd[o], c0 = sBias[o];
        float i1 = sInv[o+1], a1 = sAdd[o+1], c1 = sBias[o+1];
        float* p0 = out + ((size_t)(b*64 + o))*HW + h*128;
        float* p1 = p0 + HW;
        p0[w0 + g]     = fmaxf((acc[nt][0] + c0)*i0 + a0, 0.f);
        p1[w0 + g]     = fmaxf((acc[nt][1] + c1)*i1 + a1, 0.f);
        p0[w0 + g + 8] = fmaxf((acc[nt][2] + c0)*i0 + a0, 0.f);
        p1[w0 + g + 8] = fmaxf((acc[nt][3] + c1)*i1 + a1, 0.f);
    }
}

// ---------------- host --------------------------------------------------------
extern "C" void kernel_launch(void* const* d_in, const int* in_sizes, int n_in,
                              void* d_out, int out_size)
{
    const float* x     = (const float*)d_in[0];
    const float* kern  = (const float*)d_in[1];
    const float* mw    = (const float*)d_in[2];
    const float* mb    = (const float*)d_in[3];
    const float* cow   = (const float*)d_in[4];
    const float* cob   = (const float*)d_in[5];
    const float* gamma = (const float*)d_in[6];
    const float* beta  = (const float*)d_in[7];
    const float* mean  = (const float*)d_in[8];
    const float* var   = (const float*)d_in[9];
    float* out   = (float*)d_out;
    float* masks = out + 4*64*HW;

    const int SMEM_BR  = 2 * 27648;   // 55296 -> 3 CTAs/SM (reg-capped)
    const int SMEM_OUT = 2 * 46080;   // 92160 -> 2 CTAs/SM
    cudaFuncSetAttribute(branch_mma, cudaFuncAttributeMaxDynamicSharedMemorySize, SMEM_BR);
    cudaFuncSetAttribute(out_mma,    cudaFuncAttributeMaxDynamicSharedMemorySize, SMEM_OUT);

    mask_kernel<<<256, 256>>>(x, mw, mb, masks);
    xmT_kernel<<<1536, 256>>>(x, masks);
    wprep_kernel<<<1728, 256>>>(kern, cow);
    branch_mma<<<2048, 256, SMEM_BR>>>();
    out_mma<<<512, 256, SMEM_OUT>>>(cob, gamma, beta, mean, var, out);
}

// round 14
// speedup vs baseline: 2.6281x; 1.1673x over previous
#include <cuda_runtime.h>
#include <cuda_fp16.h>
#include <stdint.h>
#include <math.h>

#define HW 16384
#define RLEN 9088         // padded row: 448 + 128*64 + 448 elems
#define NROWS 144         // h = -8 .. 135
typedef unsigned u32; typedef unsigned long long u64;

// ---------------- device scratch (zero-initialized; pads never written) ----
__device__ __align__(256) __half g_xA_h[12 * NROWS * RLEN];
__device__ __align__(256) __half g_cA_h[16 * NROWS * RLEN];
__device__ __align__(256) __half g_wb_h[4 * 27 * 4096];
__device__ __align__(256) __half g_wo_h[36 * 4096];

// ---------------- PTX helpers ----------------------------------------------
__device__ __forceinline__ u32 s2u(const void* p){
    u32 a; asm("{ .reg .u64 t; cvta.to.shared.u64 t, %1; cvt.u32.u64 %0, t; }"
               : "=r"(a) : "l"(p)); return a;
}
#define CP16(dst, src) \
    asm volatile("cp.async.cg.shared.global [%0], [%1], 16;" :: "r"(dst), "l"(src) : "memory")
#define CP_COMMIT() asm volatile("cp.async.commit_group;" ::: "memory")
#define CP_WAIT1()  asm volatile("cp.async.wait_group 1;" ::: "memory")
#define LDX4(r, a) \
    asm volatile("ldmatrix.sync.aligned.m8n8.x4.shared.b16 {%0,%1,%2,%3}, [%4];" \
        : "=r"((r)[0]), "=r"((r)[1]), "=r"((r)[2]), "=r"((r)[3]) : "r"(a))
#define MMA(d, a, b0, b1) \
    asm("mma.sync.aligned.m16n8k16.row.col.f32.f16.f16.f32 " \
        "{%0,%1,%2,%3},{%4,%5,%6,%7},{%8,%9},{%0,%1,%2,%3};" \
        : "+f"((d)[0]), "+f"((d)[1]), "+f"((d)[2]), "+f"((d)[3]) \
        : "r"((a)[0]), "r"((a)[1]), "r"((a)[2]), "r"((a)[3]), "r"(b0), "r"(b1))

__device__ __forceinline__ u32 pack2h(float v0, float v1){
    __half h0 = __float2half_rn(v0);
    __half h1 = __float2half_rn(v1);
    return (u32)*(unsigned short*)&h0 | ((u32)*(unsigned short*)&h1 << 16);
}

// ---------------- stage 1: mask conv + softmax ------------------------------
__global__ void mask_kernel(const float* __restrict__ x, const float* __restrict__ mw,
                            const float* __restrict__ mb, float* __restrict__ masks)
{
    __shared__ float s_mw[3*64*9];
    for (int i = threadIdx.x; i < 3*64*9; i += 256) s_mw[i] = mw[i];
    __syncthreads();
    int gid = blockIdx.x*256 + threadIdx.x;
    int b = gid >> 14, pid = gid & (HW-1), h = pid >> 7, w = pid & 127;
    float a0 = mb[0], a1 = mb[1], a2 = mb[2];
    const float* xb = x + b*64*HW;
    for (int c = 0; c < 64; c++){
        const float* xc = xb + c*HW; const float* wc = s_mw + c*9;
        #pragma unroll
        for (int kh = 0; kh < 3; kh++){
            int hh = h + kh - 1; if ((unsigned)hh >= 128u) continue;
            #pragma unroll
            for (int kw = 0; kw < 3; kw++){
                int ww = w + kw - 1; if ((unsigned)ww >= 128u) continue;
                float v = xc[hh*128 + ww]; int t = kh*3 + kw;
                a0 = fmaf(v, wc[t], a0); a1 = fmaf(v, wc[576+t], a1); a2 = fmaf(v, wc[1152+t], a2);
            }
        }
    }
    float mx = fmaxf(a0, fmaxf(a1, a2));
    float e0 = expf(a0-mx), e1 = expf(a1-mx), e2 = expf(a2-mx);
    float inv = 1.f/(e0+e1+e2);
    masks[(b*3+0)*HW+pid] = e0*inv; masks[(b*3+1)*HW+pid] = e1*inv; masks[(b*3+2)*HW+pid] = e2*inv;
}

// ---------------- stage 2: transpose xm into padded fp16 layout -------------
__global__ void xmT_kernel(const float* __restrict__ x, const float* __restrict__ masks)
{
    __shared__ float sx[64*129];
    __shared__ float sm[128];
    int bx = blockIdx.x;                 // (bm<<7)|h
    int h = bx & 127, bm = bx >> 7, m = bm % 3, b = bm / 3;
    for (int idx = threadIdx.x; idx < 8192; idx += 256){
        int c = idx >> 7, w = idx & 127;
        sx[c*129 + w] = x[(b*64 + c)*HW + h*128 + w];
    }
    if (threadIdx.x < 128) sm[threadIdx.x] = masks[bm*HW + h*128 + threadIdx.x];
    __syncthreads();
    size_t base = ((size_t)bm*NROWS + (h+8))*RLEN + 448;
    for (int idx = threadIdx.x; idx < 4096; idx += 256){
        int w = idx >> 5, c2 = (idx & 31)*2;
        float v0 = sx[c2*129 + w] * sm[w];
        float v1 = sx[(c2+1)*129 + w] * sm[w];
        *(u32*)(g_xA_h + base + (size_t)w*64 + c2) = pack2h(v0, v1);
    }
}

// ---------------- weight prep: fp16 B tiles [tile][o][c] --------------------
__global__ void wprep_kernel(const float* __restrict__ kern, const float* __restrict__ cow)
{
    int i = blockIdx.x*256 + threadIdx.x;
    if (i < 4*27*4096){
        int tile = i >> 12, e = i & 4095, o = e >> 6, c = e & 63;
        int b = tile / 27, r = tile % 27, tap = r / 3, m = r % 3;
        g_wb_h[i] = __float2half_rn(kern[(((b*3 + m)*64 + o)*64 + c)*9 + tap]);
    }
    if (i < 36*4096){
        int tile = i >> 12, e = i & 4095, o = e >> 6, c = e & 63;
        int tap = tile / 4, ch = tile % 4;
        g_wo_h[i] = __float2half_rn(cow[(o*256 + ch*64 + c)*9 + tap]);
    }
}

// ---------------- MMA mainloop: 256 threads, M=128, double-buffered ---------
// Single fp16 A and B: stage = A 18432 + B 9216 = 27648 bytes -> 3 CTAs/SM
template<int NS, int NCH>
__device__ __forceinline__ void mma_mainloop(
    const __half* __restrict__ xah, const __half* __restrict__ wth,
    int d, int h, float acc[8][4])
{
    constexpr u32 B_OFF = 18432u;
    constexpr u32 BUFSZ = 27648u;

    extern __shared__ __align__(16) unsigned char smraw[];
    u32 sm0 = s2u(smraw);
    const int tid = threadIdx.x, lane = tid & 31, wid = tid >> 5;

    #pragma unroll
    for (int i = 0; i < 8; i++)
        #pragma unroll
        for (int j = 0; j < 4; j++) acc[i][j] = 0.f;

    auto issue = [&](int s, int buf){
        int tap = s / NCH, ch = s - tap*NCH;
        int dh = (tap/3 - 1)*d, dw = (tap%3 - 1)*d;
        size_t arow = ((size_t)ch*NROWS + (h + 8 + dh))*RLEN + 448 + (long)dw*64;
        u32 abase = sm0 + (u32)buf*BUFSZ;
        #pragma unroll
        for (int t = 0; t < 4; t++){
            int idx = tid + t*256; int w = idx >> 3, c16 = idx & 7;
            CP16(abase + (u32)(w*144 + c16*16), xah + arow + (size_t)w*64 + c16*8);
        }
        u32 bbase = abase + B_OFF;
        const __half* wsh = wth + (size_t)s*4096;
        #pragma unroll
        for (int t = 0; t < 2; t++){
            int idx = tid + t*256; int o = idx >> 3, c16 = idx & 7;
            CP16(bbase + (u32)(o*144 + c16*16), wsh + o*64 + c16*8);
        }
    };

    issue(0, 0); CP_COMMIT();
    issue(1, 1); CP_COMMIT();

    const u32 a_lane = (u32)((wid*16 + (lane & 15))*144 + (lane >> 4)*16);
    const int br = lane & 7, bq = lane >> 3;
    const u32 b_lane0 = (u32)((br + (bq >> 1)*8)*144 + (bq & 1)*16);

    for (int s = 0; s < NS; s++){
        int buf = s & 1;
        CP_WAIT1();
        __syncthreads();
        u32 ab = sm0 + (u32)buf*BUFSZ + a_lane;
        u32 bb = sm0 + (u32)buf*BUFSZ + B_OFF + b_lane0;
        #pragma unroll
        for (int ks = 0; ks < 4; ks++){
            u32 ah[4];
            LDX4(ah, ab + ks*32);
            #pragma unroll
            for (int np = 0; np < 4; np++){
                u32 bh[4];
                LDX4(bh, bb + (u32)(np*16*144) + ks*32);
                MMA(acc[2*np],   ah, bh[0], bh[1]);
                MMA(acc[2*np+1], ah, bh[2], bh[3]);
            }
        }
        __syncthreads();
        if (s + 2 < NS) issue(s + 2, buf);
        CP_COMMIT();
    }
}

// ---------------- branch conv: writes fp16 cat tiles -------------------------
__global__ void __launch_bounds__(256, 3)
branch_mma()
{
    int bx = blockIdx.x;                  // h | di<<7 | b<<9
    int h = bx & 127, di = (bx >> 7) & 3, b = bx >> 9;
    int d = 2*di + 1;

    float acc[8][4];
    mma_mainloop<27, 3>(g_xA_h + (size_t)(b*3)*NROWS*RLEN,
                        g_wb_h + (size_t)b*27*4096, d, h, acc);

    const int lane = threadIdx.x & 31, wid = threadIdx.x >> 5;
    const int w0 = wid*16, g = lane >> 2, tig = lane & 3;
    size_t cb = ((size_t)(b*4 + di)*NROWS + (h + 8))*RLEN + 448;
    #pragma unroll
    for (int nt = 0; nt < 8; nt++){
        int o = nt*8 + 2*tig;
        *(u32*)(g_cA_h + cb + (size_t)(w0 + g)*64 + o)     = pack2h(acc[nt][0], acc[nt][1]);
        *(u32*)(g_cA_h + cb + (size_t)(w0 + g + 8)*64 + o) = pack2h(acc[nt][2], acc[nt][3]);
    }
}

// ---------------- out conv + bias + BN + ReLU --------------------------------
__global__ void __launch_bounds__(256, 3)
out_mma(const float* __restrict__ cob, const float* __restrict__ gamma,
        const float* __restrict__ beta, const float* __restrict__ mean,
        const float* __restrict__ var, float* __restrict__ out)
{
    __shared__ float sInv[64], sAdd[64], sBias[64];
    int bx = blockIdx.x;                  // h | b<<7
    int h = bx & 127, b = bx >> 7;
    if (threadIdx.x < 64){
        int o = threadIdx.x;
        float inv = gamma[o] * rsqrtf(var[o] + 1e-5f);
        sInv[o] = inv; sAdd[o] = beta[o] - mean[o]*inv; sBias[o] = cob[o];
    }

    float acc[8][4];
    mma_mainloop<36, 4>(g_cA_h + (size_t)(b*4)*NROWS*RLEN, g_wo_h, 1, h, acc);

    const int lane = threadIdx.x & 31, wid = threadIdx.x >> 5;
    const int w0 = wid*16, g = lane >> 2, tig = lane & 3;
    #pragma unroll
    for (int nt = 0; nt < 8; nt++){
        int o = nt*8 + 2*tig;
        float i0 = sInv[o], a0 = sAdd[o], c0 = sBias[o];
        float i1 = sInv[o+1], a1 = sAdd[o+1], c1 = sBias[o+1];
        float* p0 = out + ((size_t)(b*64 + o))*HW + h*128;
        float* p1 = p0 + HW;
        p0[w0 + g]     = fmaxf((acc[nt][0] + c0)*i0 + a0, 0.f);
        p1[w0 + g]     = fmaxf((acc[nt][1] + c1)*i1 + a1, 0.f);
        p0[w0 + g + 8] = fmaxf((acc[nt][2] + c0)*i0 + a0, 0.f);
        p1[w0 + g + 8] = fmaxf((acc[nt][3] + c1)*i1 + a1, 0.f);
    }
}

// ---------------- host --------------------------------------------------------
extern "C" void kernel_launch(void* const* d_in, const int* in_sizes, int n_in,
                              void* d_out, int out_size)
{
    const float* x     = (const float*)d_in[0];
    const float* kern  = (const float*)d_in[1];
    const float* mw    = (const float*)d_in[2];
    const float* mb    = (const float*)d_in[3];
    const float* cow   = (const float*)d_in[4];
    const float* cob   = (const float*)d_in[5];
    const float* gamma = (const float*)d_in[6];
    const float* beta  = (const float*)d_in[7];
    const float* mean  = (const float*)d_in[8];
    const float* var   = (const float*)d_in[9];
    float* out   = (float*)d_out;
    float* masks = out + 4*64*HW;

    const int SMEM = 2 * 27648;   // 55296 -> 3 CTAs/SM
    cudaFuncSetAttribute(branch_mma, cudaFuncAttributeMaxDynamicSharedMemorySize, SMEM);
    cudaFuncSetAttribute(out_mma,    cudaFuncAttributeMaxDynamicSharedMemorySize, SMEM);

    mask_kernel<<<256, 256>>>(x, mw, mb, masks);
    xmT_kernel<<<1536, 256>>>(x, masks);
    wprep_kernel<<<1728, 256>>>(kern, cow);
    branch_mma<<<2048, 256, SMEM>>>();
    out_mma<<<512, 256, SMEM>>>(cob, gamma, beta, mean, var, out);
}

// round 15
// speedup vs baseline: 2.9848x; 1.1357x over previous
#include <cuda_runtime.h>
#include <cuda_fp16.h>
#include <stdint.h>
#include <math.h>

#define HW 16384
#define RLEN 9088         // padded row: 448 + 128*64 + 448 elems (7-px pads)
#define NROWS 144         // h = -8 .. 135
typedef unsigned u32; typedef unsigned long long u64;

// ---------------- device scratch (zero-initialized; pads never written) ----
__device__ __align__(256) __half g_xA_h[12 * NROWS * RLEN];
__device__ __align__(256) __half g_cA_h[16 * NROWS * RLEN];
__device__ __align__(256) __half g_wb_h[4 * 27 * 4096];
__device__ __align__(256) __half g_wo_h[36 * 4096];

// ---------------- PTX helpers ----------------------------------------------
__device__ __forceinline__ u32 s2u(const void* p){
    u32 a; asm("{ .reg .u64 t; cvta.to.shared.u64 t, %1; cvt.u32.u64 %0, t; }"
               : "=r"(a) : "l"(p)); return a;
}
#define CP16(dst, src) \
    asm volatile("cp.async.cg.shared.global [%0], [%1], 16;" :: "r"(dst), "l"(src) : "memory")
#define CP_COMMIT() asm volatile("cp.async.commit_group;" ::: "memory")
#define CP_WAIT1()  asm volatile("cp.async.wait_group 1;" ::: "memory")
#define LDX4(r, a) \
    asm volatile("ldmatrix.sync.aligned.m8n8.x4.shared.b16 {%0,%1,%2,%3}, [%4];" \
        : "=r"((r)[0]), "=r"((r)[1]), "=r"((r)[2]), "=r"((r)[3]) : "r"(a))
#define MMA(d, a, b0, b1) \
    asm("mma.sync.aligned.m16n8k16.row.col.f32.f16.f16.f32 " \
        "{%0,%1,%2,%3},{%4,%5,%6,%7},{%8,%9},{%0,%1,%2,%3};" \
        : "+f"((d)[0]), "+f"((d)[1]), "+f"((d)[2]), "+f"((d)[3]) \
        : "r"((a)[0]), "r"((a)[1]), "r"((a)[2]), "r"((a)[3]), "r"(b0), "r"(b1))

__device__ __forceinline__ u32 pack2h(float v0, float v1){
    __half h0 = __float2half_rn(v0);
    __half h1 = __float2half_rn(v1);
    return (u32)*(unsigned short*)&h0 | ((u32)*(unsigned short*)&h1 << 16);
}

// ---------------- stage 1: mask conv + softmax ------------------------------
__global__ void mask_kernel(const float* __restrict__ x, const float* __restrict__ mw,
                            const float* __restrict__ mb, float* __restrict__ masks)
{
    __shared__ float s_mw[3*64*9];
    for (int i = threadIdx.x; i < 3*64*9; i += 256) s_mw[i] = mw[i];
    __syncthreads();
    int gid = blockIdx.x*256 + threadIdx.x;
    int b = gid >> 14, pid = gid & (HW-1), h = pid >> 7, w = pid & 127;
    float a0 = mb[0], a1 = mb[1], a2 = mb[2];
    const float* xb = x + b*64*HW;
    for (int c = 0; c < 64; c++){
        const float* xc = xb + c*HW; const float* wc = s_mw + c*9;
        #pragma unroll
        for (int kh = 0; kh < 3; kh++){
            int hh = h + kh - 1; if ((unsigned)hh >= 128u) continue;
            #pragma unroll
            for (int kw = 0; kw < 3; kw++){
                int ww = w + kw - 1; if ((unsigned)ww >= 128u) continue;
                float v = xc[hh*128 + ww]; int t = kh*3 + kw;
                a0 = fmaf(v, wc[t], a0); a1 = fmaf(v, wc[576+t], a1); a2 = fmaf(v, wc[1152+t], a2);
            }
        }
    }
    float mx = fmaxf(a0, fmaxf(a1, a2));
    float e0 = expf(a0-mx), e1 = expf(a1-mx), e2 = expf(a2-mx);
    float inv = 1.f/(e0+e1+e2);
    masks[(b*3+0)*HW+pid] = e0*inv; masks[(b*3+1)*HW+pid] = e1*inv; masks[(b*3+2)*HW+pid] = e2*inv;
}

// ---------------- stage 2: transpose xm into padded fp16 layout -------------
__global__ void xmT_kernel(const float* __restrict__ x, const float* __restrict__ masks)
{
    __shared__ float sx[64*129];
    __shared__ float sm[128];
    int bx = blockIdx.x;                 // (bm<<7)|h
    int h = bx & 127, bm = bx >> 7, m = bm % 3, b = bm / 3;
    for (int idx = threadIdx.x; idx < 8192; idx += 256){
        int c = idx >> 7, w = idx & 127;
        sx[c*129 + w] = x[(b*64 + c)*HW + h*128 + w];
    }
    if (threadIdx.x < 128) sm[threadIdx.x] = masks[bm*HW + h*128 + threadIdx.x];
    __syncthreads();
    size_t base = ((size_t)bm*NROWS + (h+8))*RLEN + 448;
    for (int idx = threadIdx.x; idx < 4096; idx += 256){
        int w = idx >> 5, c2 = (idx & 31)*2;
        float v0 = sx[c2*129 + w] * sm[w];
        float v1 = sx[(c2+1)*129 + w] * sm[w];
        *(u32*)(g_xA_h + base + (size_t)w*64 + c2) = pack2h(v0, v1);
    }
}

// ---------------- weight prep: fp16 B tiles [tile][o][c] --------------------
__global__ void wprep_kernel(const float* __restrict__ kern, const float* __restrict__ cow)
{
    int i = blockIdx.x*256 + threadIdx.x;
    if (i < 4*27*4096){
        int tile = i >> 12, e = i & 4095, o = e >> 6, c = e & 63;
        int b = tile / 27, r = tile % 27, tap = r / 3, m = r % 3;
        g_wb_h[i] = __float2half_rn(kern[(((b*3 + m)*64 + o)*64 + c)*9 + tap]);
    }
    if (i < 36*4096){
        int tile = i >> 12, e = i & 4095, o = e >> 6, c = e & 63;
        int tap = tile / 4, ch = tile % 4;
        g_wo_h[i] = __float2half_rn(cow[(o*256 + ch*64 + c)*9 + tap]);
    }
}

// ---------------- MMA mainloop: M=256 (2 output rows), 256 thr, dbl-buffer --
// Stage: A 256x72 fp16 (36864B) + B 64x72 (9216B) = 46080B; 2 stages -> 2 CTA/SM.
// Each of 8 warps: 2x m16 (rows h0, h0+1) x n64 -> 64 MMA, 24 LDX4 per stage.
template<int NS, int NCH>
__device__ __forceinline__ void mma_mainloop(
    const __half* __restrict__ xah, const __half* __restrict__ wth,
    int d, int h0, float acc0[8][4], float acc1[8][4])
{
    constexpr u32 B_OFF = 36864u;
    constexpr u32 BUFSZ = 46080u;

    extern __shared__ __align__(16) unsigned char smraw[];
    u32 sm0 = s2u(smraw);
    const int tid = threadIdx.x, lane = tid & 31, wid = tid >> 5;

    #pragma unroll
    for (int i = 0; i < 8; i++)
        #pragma unroll
        for (int j = 0; j < 4; j++){ acc0[i][j] = 0.f; acc1[i][j] = 0.f; }

    auto issue = [&](int s, int buf){
        int tap = s / NCH, ch = s - tap*NCH;
        int dh = (tap/3 - 1)*d, dw = (tap%3 - 1)*d;
        size_t arow = ((size_t)ch*NROWS + (h0 + 8 + dh))*RLEN + 448 + (long)dw*64;
        u32 abase = sm0 + (u32)buf*BUFSZ;
        #pragma unroll
        for (int t = 0; t < 8; t++){
            int idx = tid + t*256;            // < 2048
            int r = idx >> 3, c16 = idx & 7;  // r: 0..255 (r>>7 selects h row)
            size_t off = arow + (size_t)(r >> 7)*RLEN + (size_t)(r & 127)*64 + c16*8;
            CP16(abase + (u32)(r*144 + c16*16), xah + off);
        }
        u32 bbase = abase + B_OFF;
        const __half* wsh = wth + (size_t)s*4096;
        #pragma unroll
        for (int t = 0; t < 2; t++){
            int idx = tid + t*256; int o = idx >> 3, c16 = idx & 7;
            CP16(bbase + (u32)(o*144 + c16*16), wsh + o*64 + c16*8);
        }
    };

    issue(0, 0); CP_COMMIT();
    issue(1, 1); CP_COMMIT();

    const u32 a_lane = (u32)((wid*16 + (lane & 15))*144 + (lane >> 4)*16);
    const int br = lane & 7, bq = lane >> 3;
    const u32 b_lane0 = (u32)((br + (bq >> 1)*8)*144 + (bq & 1)*16);

    for (int s = 0; s < NS; s++){
        int buf = s & 1;
        CP_WAIT1();
        __syncthreads();
        u32 ab0 = sm0 + (u32)buf*BUFSZ + a_lane;
        u32 ab1 = ab0 + 128u*144u;
        u32 bb  = sm0 + (u32)buf*BUFSZ + B_OFF + b_lane0;
        #pragma unroll
        for (int ks = 0; ks < 4; ks++){
            u32 ah0[4], ah1[4];
            LDX4(ah0, ab0 + ks*32);
            LDX4(ah1, ab1 + ks*32);
            #pragma unroll
            for (int np = 0; np < 4; np++){
                u32 bh[4];
                LDX4(bh, bb + (u32)(np*16*144) + ks*32);
                MMA(acc0[2*np],   ah0, bh[0], bh[1]);
                MMA(acc0[2*np+1], ah0, bh[2], bh[3]);
                MMA(acc1[2*np],   ah1, bh[0], bh[1]);
                MMA(acc1[2*np+1], ah1, bh[2], bh[3]);
            }
        }
        __syncthreads();
        if (s + 2 < NS) issue(s + 2, buf);
        CP_COMMIT();
    }
}

// ---------------- branch conv: writes fp16 cat tiles -------------------------
__global__ void __launch_bounds__(256, 2)
branch_mma()
{
    int bx = blockIdx.x;                  // hp | di<<6 | b<<8
    int hp = bx & 63, di = (bx >> 6) & 3, b = bx >> 8;
    int d = 2*di + 1, h0 = hp*2;

    float acc0[8][4], acc1[8][4];
    mma_mainloop<27, 3>(g_xA_h + (size_t)(b*3)*NROWS*RLEN,
                        g_wb_h + (size_t)b*27*4096, d, h0, acc0, acc1);

    const int lane = threadIdx.x & 31, wid = threadIdx.x >> 5;
    const int w0 = wid*16, g = lane >> 2, tig = lane & 3;
    size_t cb0 = ((size_t)(b*4 + di)*NROWS + (h0 + 8))*RLEN + 448;
    size_t cb1 = cb0 + RLEN;
    #pragma unroll
    for (int nt = 0; nt < 8; nt++){
        int o = nt*8 + 2*tig;
        *(u32*)(g_cA_h + cb0 + (size_t)(w0 + g)*64 + o)     = pack2h(acc0[nt][0], acc0[nt][1]);
        *(u32*)(g_cA_h + cb0 + (size_t)(w0 + g + 8)*64 + o) = pack2h(acc0[nt][2], acc0[nt][3]);
        *(u32*)(g_cA_h + cb1 + (size_t)(w0 + g)*64 + o)     = pack2h(acc1[nt][0], acc1[nt][1]);
        *(u32*)(g_cA_h + cb1 + (size_t)(w0 + g + 8)*64 + o) = pack2h(acc1[nt][2], acc1[nt][3]);
    }
}

// ---------------- out conv + bias + BN + ReLU --------------------------------
__global__ void __launch_bounds__(256, 2)
out_mma(const float* __restrict__ cob, const float* __restrict__ gamma,
        const float* __restrict__ beta, const float* __restrict__ mean,
        const float* __restrict__ var, float* __restrict__ out)
{
    __shared__ float sInv[64], sAdd[64], sBias[64];
    int bx = blockIdx.x;                  // hp | b<<6
    int hp = bx & 63, b = bx >> 6;
    int h0 = hp*2;
    if (threadIdx.x < 64){
        int o = threadIdx.x;
        float inv = gamma[o] * rsqrtf(var[o] + 1e-5f);
        sInv[o] = inv; sAdd[o] = beta[o] - mean[o]*inv; sBias[o] = cob[o];
    }

    float acc0[8][4], acc1[8][4];
    mma_mainloop<36, 4>(g_cA_h + (size_t)(b*4)*NROWS*RLEN, g_wo_h, 1, h0, acc0, acc1);

    const int lane = threadIdx.x & 31, wid = threadIdx.x >> 5;
    const int w0 = wid*16, g = lane >> 2, tig = lane & 3;
    #pragma unroll
    for (int nt = 0; nt < 8; nt++){
        int o = nt*8 + 2*tig;
        float i0 = sInv[o], a0 = sAdd[o], c0 = sBias[o];
        float i1 = sInv[o+1], a1 = sAdd[o+1], c1 = sBias[o+1];
        float* p0 = out + ((size_t)(b*64 + o))*HW + h0*128;
        float* p1 = p0 + HW;
        p0[w0 + g]           = fmaxf((acc0[nt][0] + c0)*i0 + a0, 0.f);
        p1[w0 + g]           = fmaxf((acc0[nt][1] + c1)*i1 + a1, 0.f);
        p0[w0 + g + 8]       = fmaxf((acc0[nt][2] + c0)*i0 + a0, 0.f);
        p1[w0 + g + 8]       = fmaxf((acc0[nt][3] + c1)*i1 + a1, 0.f);
        p0[128 + w0 + g]     = fmaxf((acc1[nt][0] + c0)*i0 + a0, 0.f);
        p1[128 + w0 + g]     = fmaxf((acc1[nt][1] + c1)*i1 + a1, 0.f);
        p0[128 + w0 + g + 8] = fmaxf((acc1[nt][2] + c0)*i0 + a0, 0.f);
        p1[128 + w0 + g + 8] = fmaxf((acc1[nt][3] + c1)*i1 + a1, 0.f);
    }
}

// ---------------- host --------------------------------------------------------
extern "C" void kernel_launch(void* const* d_in, const int* in_sizes, int n_in,
                              void* d_out, int out_size)
{
    const float* x     = (const float*)d_in[0];
    const float* kern  = (const float*)d_in[1];
    const float* mw    = (const float*)d_in[2];
    const float* mb    = (const float*)d_in[3];
    const float* cow   = (const float*)d_in[4];
    const float* cob   = (const float*)d_in[5];
    const float* gamma = (const float*)d_in[6];
    const float* beta  = (const float*)d_in[7];
    const float* mean  = (const float*)d_in[8];
    const float* var   = (const float*)d_in[9];
    float* out   = (float*)d_out;
    float* masks = out + 4*64*HW;

    const int SMEM = 2 * 46080;   // 92160 -> 2 CTAs/SM
    cudaFuncSetAttribute(branch_mma, cudaFuncAttributeMaxDynamicSharedMemorySize, SMEM);
    cudaFuncSetAttribute(out_mma,    cudaFuncAttributeMaxDynamicSharedMemorySize, SMEM);

    mask_kernel<<<256, 256>>>(x, mw, mb, masks);
    xmT_kernel<<<1536, 256>>>(x, masks);
    wprep_kernel<<<1728, 256>>>(kern, cow);
    branch_mma<<<1024, 256, SMEM>>>();
    out_mma<<<256, 256, SMEM>>>(cob, gamma, beta, mean, var, out);
}